// round 6
// baseline (speedup 1.0000x reference)
#include <cuda_runtime.h>
#include <cuda_bf16.h>
#include <math.h>
#include <cstdint>

// Problem dims (fixed by the reference)
#define Tn 2048
#define Bn 2
#define En 1024
#define Hn 16
#define Dn 64
#define BHn 32          // B*H
#define Pn 3072         // 3*E
#define Kdim 1024       // K of both GEMMs
#define Mrows 4096      // T*B

// ---------------------------------------------------------------------------
// Scratch: __device__ globals (allocation-free, graph-capturable)
// ---------------------------------------------------------------------------
__device__ __nv_bfloat16 gx_hi[(size_t)Mrows * Kdim];
__device__ __nv_bfloat16 gx_lo[(size_t)Mrows * Kdim];
__device__ __nv_bfloat16 gwin_hi[(size_t)Pn * Kdim];   // in_proj_w^T  [N][K]
__device__ __nv_bfloat16 gwin_lo[(size_t)Pn * Kdim];
__device__ __nv_bfloat16 gwout_hi[(size_t)En * Kdim];  // out_w^T      [N][K]
__device__ __nv_bfloat16 gwout_lo[(size_t)En * Kdim];
__device__ __nv_bfloat16 gctx_hi[(size_t)Mrows * Kdim];
__device__ __nv_bfloat16 gctx_lo[(size_t)Mrows * Kdim];
// q/k/v splits, layout [(b*H+h)][t][d]; q pre-scaled by 0.125
__device__ __nv_bfloat16 gq_hi[(size_t)BHn * Tn * Dn];
__device__ __nv_bfloat16 gq_lo[(size_t)BHn * Tn * Dn];
__device__ __nv_bfloat16 gk_hi[(size_t)BHn * Tn * Dn];
__device__ __nv_bfloat16 gk_lo[(size_t)BHn * Tn * Dn];
__device__ __nv_bfloat16 gv_hi[(size_t)BHn * Tn * Dn];
__device__ __nv_bfloat16 gv_lo[(size_t)BHn * Tn * Dn];

// ---------------------------------------------------------------------------
// PTX helpers (sm_103-safe: mma.sync + ldmatrix + cp.async only)
// ---------------------------------------------------------------------------
__device__ __forceinline__ uint32_t smem_u32(const void* p) {
  uint32_t a;
  asm("{ .reg .u64 t; cvta.to.shared.u64 t, %1; cvt.u32.u64 %0, t; }"
      : "=r"(a) : "l"(p));
  return a;
}

#define SW128(off) ((uint32_t)(off) ^ ((((uint32_t)(off)) >> 3) & 0x70))
#define SW64(off)  ((uint32_t)(off) ^ ((((uint32_t)(off)) >> 3) & 0x30))

#define CP_ASYNC16(dst, src)                                       \
  asm volatile("cp.async.cg.shared.global [%0], [%1], 16;"         \
               :: "r"(dst), "l"(src) : "memory")
#define CP_COMMIT() asm volatile("cp.async.commit_group;" ::: "memory")
#define CP_WAIT(n) asm volatile("cp.async.wait_group %0;" :: "n"(n) : "memory")

__device__ __forceinline__ void ldmx4(uint32_t* r, uint32_t addr) {
  asm volatile(
      "ldmatrix.sync.aligned.m8n8.x4.shared.b16 {%0,%1,%2,%3}, [%4];"
      : "=r"(r[0]), "=r"(r[1]), "=r"(r[2]), "=r"(r[3]) : "r"(addr));
}
__device__ __forceinline__ void ldmx4t(uint32_t* r, uint32_t addr) {
  asm volatile(
      "ldmatrix.sync.aligned.m8n8.x4.trans.shared.b16 {%0,%1,%2,%3}, [%4];"
      : "=r"(r[0]), "=r"(r[1]), "=r"(r[2]), "=r"(r[3]) : "r"(addr));
}

__device__ __forceinline__ void mma16816(float* c, const uint32_t* a,
                                         const uint32_t* b) {
  asm volatile(
      "mma.sync.aligned.m16n8k16.row.col.f32.bf16.bf16.f32 "
      "{%0,%1,%2,%3}, {%4,%5,%6,%7}, {%8,%9}, {%0,%1,%2,%3};"
      : "+f"(c[0]), "+f"(c[1]), "+f"(c[2]), "+f"(c[3])
      : "r"(a[0]), "r"(a[1]), "r"(a[2]), "r"(a[3]), "r"(b[0]), "r"(b[1]));
}

// split a float pair into bf16 hi/lo packed words
__device__ __forceinline__ void split2(float p0, float p1, uint32_t& h,
                                       uint32_t& l) {
  __nv_bfloat162 hh = __float22bfloat162_rn(make_float2(p0, p1));
  __nv_bfloat162 ll = __float22bfloat162_rn(
      make_float2(p0 - __bfloat162float(hh.x), p1 - __bfloat162float(hh.y)));
  h = *(uint32_t*)&hh;
  l = *(uint32_t*)&ll;
}

// ---------------------------------------------------------------------------
// Conversion kernels: fp32 -> bf16 hi/lo split
// ---------------------------------------------------------------------------
__global__ __launch_bounds__(256) void cvt_x(const float* __restrict__ xin) {
  size_t i = ((size_t)blockIdx.x * blockDim.x + threadIdx.x) * 4;
  if (i < (size_t)Mrows * Kdim) {
    float4 v = *(const float4*)(xin + i);
    __nv_bfloat16 h[4], l[4];
    h[0] = __float2bfloat16(v.x); l[0] = __float2bfloat16(v.x - __bfloat162float(h[0]));
    h[1] = __float2bfloat16(v.y); l[1] = __float2bfloat16(v.y - __bfloat162float(h[1]));
    h[2] = __float2bfloat16(v.z); l[2] = __float2bfloat16(v.z - __bfloat162float(h[2]));
    h[3] = __float2bfloat16(v.w); l[3] = __float2bfloat16(v.w - __bfloat162float(h[3]));
    *(uint2*)(gx_hi + i) = *(uint2*)h;
    *(uint2*)(gx_lo + i) = *(uint2*)l;
  }
}

// Transpose W[K][N] -> Wt_hi/lo [N][K] (bf16 split). which: 0=in_proj, 1=out
__global__ __launch_bounds__(256) void cvt_transpose(const float* __restrict__ W,
                                                     int which) {
  __nv_bfloat16* hi = (which == 0) ? gwin_hi : gwout_hi;
  __nv_bfloat16* lo = (which == 0) ? gwin_lo : gwout_lo;
  const int N = (which == 0) ? Pn : En;
  __shared__ float t[32][33];
  const int n0 = blockIdx.x * 32, k0 = blockIdx.y * 32;
  const int tx = threadIdx.x, ty = threadIdx.y;  // 32 x 8
#pragma unroll
  for (int i = ty; i < 32; i += 8)
    t[i][tx] = W[(size_t)(k0 + i) * N + n0 + tx];
  __syncthreads();
#pragma unroll
  for (int j = ty; j < 32; j += 8) {
    float v = t[tx][j];
    __nv_bfloat16 h = __float2bfloat16(v);
    __nv_bfloat16 l = __float2bfloat16(v - __bfloat162float(h));
    hi[(size_t)(n0 + j) * Kdim + k0 + tx] = h;
    lo[(size_t)(n0 + j) * Kdim + k0 + tx] = l;
  }
}

// ---------------------------------------------------------------------------
// HMMA split-bf16 GEMM: per CTA D[128 x 128] = A[M,K] * B^T[N,K] + bias
// BK=32 chunks (SW64 smem, 32KB/stage, double-buffered = 64KB) so 2 CTAs/SM.
//   mode 0: A = x split, B = in_proj^T; epilogue -> q/k/v bf16 splits
//   mode 1: A = ctx split, B = out_w^T; epilogue -> fp32 d_out
// ---------------------------------------------------------------------------
#define GOFF_AHI 0
#define GOFF_ALO 8192
#define GOFF_BHI 16384
#define GOFF_BLO 24576
#define GSTAGE 32768
#define GEMM_SMEM (2 * GSTAGE)  // 64 KB
#define NCHUNK (Kdim / 32)      // 32

// Load one BK=32 chunk: 512 16B-vectors per operand, 2 per thread.
__device__ __forceinline__ void gemm_load_chunk(
    uint32_t sb, int kc, int tid,
    const __nv_bfloat16* __restrict__ Ahi, const __nv_bfloat16* __restrict__ Alo,
    const __nv_bfloat16* __restrict__ Bhi, const __nv_bfloat16* __restrict__ Blo,
    int m0, int n0) {
  const int k0 = kc * 32;
#pragma unroll
  for (int it = 0; it < 2; it++) {
    const int v = tid + it * 256;       // 0..511
    const int row = v >> 2;             // 0..127
    const int seg = v & 3;              // 0..3 (16B segments of 64B row)
    const uint32_t sw = SW64(row * 64 + seg * 16);
    const size_t giA = (size_t)(m0 + row) * Kdim + k0 + seg * 8;
    const size_t giB = (size_t)(n0 + row) * Kdim + k0 + seg * 8;
    CP_ASYNC16(sb + GOFF_AHI + sw, Ahi + giA);
    CP_ASYNC16(sb + GOFF_ALO + sw, Alo + giA);
    CP_ASYNC16(sb + GOFF_BHI + sw, Bhi + giB);
    CP_ASYNC16(sb + GOFF_BLO + sw, Blo + giB);
  }
}

__global__ __launch_bounds__(256, 2) void hmma_gemm(
    const float* __restrict__ bias, float* __restrict__ out, int mode) {
  extern __shared__ __align__(1024) char smc[];
  const uint32_t smem_base = smem_u32(smc);
  const int tid = threadIdx.x;
  const int wid = tid >> 5;
  const int lane = tid & 31;
  const int m0 = blockIdx.y * 128;
  const int n0 = blockIdx.x * 128;
  const int wm = (wid & 1) * 64;
  const int wn = (wid >> 1) * 32;

  const __nv_bfloat16* Ahi = (mode == 0) ? gx_hi : gctx_hi;
  const __nv_bfloat16* Alo = (mode == 0) ? gx_lo : gctx_lo;
  const __nv_bfloat16* Bhi = (mode == 0) ? gwin_hi : gwout_hi;
  const __nv_bfloat16* Blo = (mode == 0) ? gwin_lo : gwout_lo;

  float acc[4][4][4];
#pragma unroll
  for (int i = 0; i < 4; i++)
#pragma unroll
    for (int j = 0; j < 4; j++)
#pragma unroll
      for (int c = 0; c < 4; c++) acc[i][j][c] = 0.f;

  const int g = lane >> 3;
  const int rr = lane & 7;

  gemm_load_chunk(smem_base, 0, tid, Ahi, Alo, Bhi, Blo, m0, n0);
  CP_COMMIT();

  for (int c = 0; c < NCHUNK; c++) {
    const int buf = c & 1;
    if (c < NCHUNK - 1) {
      gemm_load_chunk(smem_base + (1 - buf) * GSTAGE, c + 1, tid, Ahi, Alo,
                      Bhi, Blo, m0, n0);
      CP_COMMIT();
      CP_WAIT(1);
    } else {
      CP_WAIT(0);
    }
    __syncthreads();

    const uint32_t sb = smem_base + buf * GSTAGE;
#pragma unroll
    for (int ks = 0; ks < 2; ks++) {
      uint32_t aH[4][4], aL[4][4], bH[2][4], bL[2][4];
#pragma unroll
      for (int i = 0; i < 4; i++) {
        int row = wm + i * 16 + (g & 1) * 8 + rr;
        uint32_t off = SW64(row * 64 + ks * 32 + (g >> 1) * 16);
        ldmx4(aH[i], sb + GOFF_AHI + off);
        ldmx4(aL[i], sb + GOFF_ALO + off);
      }
#pragma unroll
      for (int jj = 0; jj < 2; jj++) {
        int row = wn + jj * 16 + (g >> 1) * 8 + rr;
        uint32_t off = SW64(row * 64 + ks * 32 + (g & 1) * 16);
        ldmx4(bH[jj], sb + GOFF_BHI + off);
        ldmx4(bL[jj], sb + GOFF_BLO + off);
      }
#pragma unroll
      for (int i = 0; i < 4; i++)
#pragma unroll
        for (int j = 0; j < 4; j++) {
          const uint32_t* bh = &bH[j >> 1][(j & 1) * 2];
          const uint32_t* bl = &bL[j >> 1][(j & 1) * 2];
          mma16816(acc[i][j], aH[i], bh);
          mma16816(acc[i][j], aH[i], bl);
          mma16816(acc[i][j], aL[i], bh);
        }
    }
    __syncthreads();
  }

  // Epilogue
#pragma unroll
  for (int i = 0; i < 4; i++) {
#pragma unroll
    for (int j = 0; j < 4; j++) {
      const int mr = m0 + wm + i * 16 + (lane >> 2);
      const int f = n0 + wn + j * 8 + (lane & 3) * 2;
      const float b0 = bias[f], b1 = bias[f + 1];
      float p00 = acc[i][j][0] + b0, p01 = acc[i][j][1] + b1;
      float p10 = acc[i][j][2] + b0, p11 = acc[i][j][3] + b1;
      if (mode == 0) {
        const int which = f >> 10;
        const int h = (f & 1023) >> 6;
        const int d0 = f & 63;
        __nv_bfloat16 *dh, *dl;
        float scale = 1.f;
        if (which == 0) { dh = gq_hi; dl = gq_lo; scale = 0.125f; }
        else if (which == 1) { dh = gk_hi; dl = gk_lo; }
        else { dh = gv_hi; dl = gv_lo; }
        p00 *= scale; p01 *= scale; p10 *= scale; p11 *= scale;
        uint32_t h0, l0, h1, l1;
        split2(p00, p01, h0, l0);
        split2(p10, p11, h1, l1);
        const int t0 = mr >> 1, bb0 = mr & 1;
        const int t1 = (mr + 8) >> 1, bb1 = (mr + 8) & 1;
        size_t i0 = ((size_t)(bb0 * Hn + h) * Tn + t0) * Dn + d0;
        size_t i1 = ((size_t)(bb1 * Hn + h) * Tn + t1) * Dn + d0;
        *(uint32_t*)(dh + i0) = h0; *(uint32_t*)(dl + i0) = l0;
        *(uint32_t*)(dh + i1) = h1; *(uint32_t*)(dl + i1) = l1;
      } else {
        *(float2*)(out + (size_t)mr * En + f) = make_float2(p00, p01);
        *(float2*)(out + (size_t)(mr + 8) * En + f) = make_float2(p10, p11);
      }
    }
  }
}

// ---------------------------------------------------------------------------
// HMMA flash attention: per CTA 128 queries x 1 head; 8 warps x 16 rows.
// K/V in 64-key chunks (hi/lo), double-buffered cp.async SW128 smem.
// __launch_bounds__(256,2): 96KB smem x2 = 192KB -> 2 CTAs/SM.
// ---------------------------------------------------------------------------
#define A_OFF_KHI 0
#define A_OFF_KLO 8192
#define A_OFF_VHI 16384
#define A_OFF_VLO 24576
#define A_STAGE 32768
#define A_OFF_QHI 65536
#define A_OFF_QLO 81920
#define ATTN_SMEM 98304

__device__ __forceinline__ void attn_load_chunk(uint32_t sb, int stg, int j0,
                                                int tid,
                                                const __nv_bfloat16* kh,
                                                const __nv_bfloat16* kl,
                                                const __nv_bfloat16* vh,
                                                const __nv_bfloat16* vl) {
  const uint32_t base = sb + stg * A_STAGE;
#pragma unroll
  for (int it = 0; it < 2; it++) {
    int vec = tid + it * 256;       // 0..511
    int r = vec >> 3, seg = vec & 7;
    uint32_t sw = SW128(r * 128 + seg * 16);
    size_t gi = ((size_t)(j0 + r)) * Dn + seg * 8;
    CP_ASYNC16(base + A_OFF_KHI + sw, kh + gi);
    CP_ASYNC16(base + A_OFF_KLO + sw, kl + gi);
    CP_ASYNC16(base + A_OFF_VHI + sw, vh + gi);
    CP_ASYNC16(base + A_OFF_VLO + sw, vl + gi);
  }
}

__global__ __launch_bounds__(256, 2) void attn_hmma() {
  extern __shared__ __align__(1024) char smc[];
  const uint32_t sb = smem_u32(smc);
  const int tid = threadIdx.x;
  const int wid = tid >> 5;
  const int lane = tid & 31;
  const int g = lane >> 3;
  const int rr = lane & 7;
  const int bh = blockIdx.y;
  const int q0 = blockIdx.x * 128;

  const __nv_bfloat16* qh = gq_hi + (size_t)bh * Tn * Dn;
  const __nv_bfloat16* ql = gq_lo + (size_t)bh * Tn * Dn;
  const __nv_bfloat16* kh = gk_hi + (size_t)bh * Tn * Dn;
  const __nv_bfloat16* kl = gk_lo + (size_t)bh * Tn * Dn;
  const __nv_bfloat16* vh = gv_hi + (size_t)bh * Tn * Dn;
  const __nv_bfloat16* vl = gv_lo + (size_t)bh * Tn * Dn;

  // Preamble: Q tile (hi/lo) + chunk 0, one commit group.
#pragma unroll
  for (int it = 0; it < 4; it++) {
    int vec = tid + it * 256;       // 0..1023
    int r = vec >> 3, seg = vec & 7;
    uint32_t sw = SW128(r * 128 + seg * 16);
    size_t gi = ((size_t)(q0 + r)) * Dn + seg * 8;
    CP_ASYNC16(sb + A_OFF_QHI + sw, qh + gi);
    CP_ASYNC16(sb + A_OFF_QLO + sw, ql + gi);
  }
  attn_load_chunk(sb, 0, 0, tid, kh, kl, vh, vl);
  CP_COMMIT();
  CP_WAIT(0);
  __syncthreads();

  // Q fragments held in registers for the whole key loop
  uint32_t qH[4][4], qL[4][4];
#pragma unroll
  for (int ks = 0; ks < 4; ks++) {
    int row = wid * 16 + (g & 1) * 8 + rr;
    uint32_t off = SW128(row * 128 + ks * 32 + (g >> 1) * 16);
    ldmx4(qH[ks], sb + A_OFF_QHI + off);
    ldmx4(qL[ks], sb + A_OFF_QLO + off);
  }

  float o[8][4];
#pragma unroll
  for (int dt = 0; dt < 8; dt++)
#pragma unroll
    for (int c = 0; c < 4; c++) o[dt][c] = 0.f;
  float m_i[2] = {-1e30f, -1e30f};
  float l_i[2] = {0.f, 0.f};

  for (int c = 0; c < 32; c++) {
    const int buf = c & 1;
    if (c < 31) {
      attn_load_chunk(sb, 1 - buf, (c + 1) * 64, tid, kh, kl, vh, vl);
      CP_COMMIT();
      CP_WAIT(1);
    } else {
      CP_WAIT(0);
    }
    __syncthreads();

    const uint32_t skh = sb + buf * A_STAGE + A_OFF_KHI;
    const uint32_t skl = sb + buf * A_STAGE + A_OFF_KLO;
    const uint32_t svh = sb + buf * A_STAGE + A_OFF_VHI;
    const uint32_t svl = sb + buf * A_STAGE + A_OFF_VLO;

    // ---- S = Q K^T (scaled: Q carries the 1/8) ----
    float s[8][4];
#pragma unroll
    for (int j = 0; j < 8; j++)
#pragma unroll
      for (int cc = 0; cc < 4; cc++) s[j][cc] = 0.f;

#pragma unroll
    for (int ks = 0; ks < 4; ks++) {
#pragma unroll
      for (int ng = 0; ng < 4; ng++) {
        uint32_t bkh[4], bkl[4];
        int row = ng * 16 + (g >> 1) * 8 + rr;
        uint32_t off = SW128(row * 128 + ks * 32 + (g & 1) * 16);
        ldmx4(bkh, skh + off);
        ldmx4(bkl, skl + off);
#pragma unroll
        for (int hf = 0; hf < 2; hf++) {
          const int j = ng * 2 + hf;
          mma16816(s[j], qH[ks], &bkh[hf * 2]);
          mma16816(s[j], qH[ks], &bkl[hf * 2]);
          mma16816(s[j], qL[ks], &bkh[hf * 2]);
        }
      }
    }

    // ---- online softmax (rows: l/4 and l/4+8) ----
#pragma unroll
    for (int r = 0; r < 2; r++) {
      float mx = -1e30f;
#pragma unroll
      for (int j = 0; j < 8; j++)
        mx = fmaxf(mx, fmaxf(s[j][2 * r], s[j][2 * r + 1]));
      mx = fmaxf(mx, __shfl_xor_sync(0xffffffffu, mx, 1));
      mx = fmaxf(mx, __shfl_xor_sync(0xffffffffu, mx, 2));
      float mnew = fmaxf(m_i[r], mx);
      float corr = __expf(m_i[r] - mnew);
      m_i[r] = mnew;
      float rs = 0.f;
#pragma unroll
      for (int j = 0; j < 8; j++) {
        float p0 = __expf(s[j][2 * r] - mnew);
        float p1 = __expf(s[j][2 * r + 1] - mnew);
        s[j][2 * r] = p0;
        s[j][2 * r + 1] = p1;
        rs += p0 + p1;
      }
      rs += __shfl_xor_sync(0xffffffffu, rs, 1);
      rs += __shfl_xor_sync(0xffffffffu, rs, 2);
      l_i[r] = l_i[r] * corr + rs;
#pragma unroll
      for (int dt = 0; dt < 8; dt++) {
        o[dt][2 * r] *= corr;
        o[dt][2 * r + 1] *= corr;
      }
    }

    // ---- O += P V ----
#pragma unroll
    for (int kk = 0; kk < 4; kk++) {
      uint32_t pH[4], pL[4];
      split2(s[2 * kk][0], s[2 * kk][1], pH[0], pL[0]);
      split2(s[2 * kk][2], s[2 * kk][3], pH[1], pL[1]);
      split2(s[2 * kk + 1][0], s[2 * kk + 1][1], pH[2], pL[2]);
      split2(s[2 * kk + 1][2], s[2 * kk + 1][3], pH[3], pL[3]);
#pragma unroll
      for (int dg = 0; dg < 4; dg++) {
        uint32_t bvh[4], bvl[4];
        int keyrow = kk * 16 + (g & 1) * 8 + rr;
        uint32_t off = SW128(keyrow * 128 + dg * 32 + (g >> 1) * 16);
        ldmx4t(bvh, svh + off);
        ldmx4t(bvl, svl + off);
#pragma unroll
        for (int hf = 0; hf < 2; hf++) {
          const int dt = dg * 2 + hf;
          mma16816(o[dt], pH, &bvh[hf * 2]);
          mma16816(o[dt], pH, &bvl[hf * 2]);
          mma16816(o[dt], pL, &bvh[hf * 2]);
        }
      }
    }
    __syncthreads();
  }

  // Epilogue: normalize, split to bf16 hi/lo, write scrambled ctx layout:
  //   ctx[b][h*128 + t/16][(t&15)*64 + d]
  const int b = bh >> 4;
  const int h = bh & 15;
#pragma unroll
  for (int r = 0; r < 2; r++) {
    const float inv = 1.0f / l_i[r];
    const int t = q0 + wid * 16 + (lane >> 2) + r * 8;
    const int row = h * 128 + (t >> 4);
    const size_t base = ((size_t)(b * Tn + row)) * En + ((t & 15) << 6);
#pragma unroll
    for (int dt = 0; dt < 8; dt++) {
      const int d = dt * 8 + (lane & 3) * 2;
      uint32_t hw, lw;
      split2(o[dt][2 * r] * inv, o[dt][2 * r + 1] * inv, hw, lw);
      *(uint32_t*)(gctx_hi + base + d) = hw;
      *(uint32_t*)(gctx_lo + base + d) = lw;
    }
  }
}

// ---------------------------------------------------------------------------
extern "C" void kernel_launch(void* const* d_in, const int* in_sizes, int n_in,
                              void* d_out, int out_size) {
  const float* x     = (const float*)d_in[0];  // (T, B, E)
  const float* w_in  = (const float*)d_in[1];  // (E, 3E)
  const float* b_in  = (const float*)d_in[2];  // (3E)
  const float* w_out = (const float*)d_in[3];  // (E, E)
  const float* b_out = (const float*)d_in[4];  // (E)
  float* out = (float*)d_out;                  // (B, T, E)

  cudaFuncSetAttribute(hmma_gemm, cudaFuncAttributeMaxDynamicSharedMemorySize,
                       GEMM_SMEM);
  cudaFuncSetAttribute(attn_hmma, cudaFuncAttributeMaxDynamicSharedMemorySize,
                       ATTN_SMEM);

  // bf16 split conversions
  cvt_x<<<(Mrows * Kdim / 4 + 255) / 256, 256>>>(x);
  cvt_transpose<<<dim3(Pn / 32, Kdim / 32), dim3(32, 8)>>>(w_in, 0);
  cvt_transpose<<<dim3(En / 32, Kdim / 32), dim3(32, 8)>>>(w_out, 1);

  // 1) QKV projection (HMMA) -> q/k/v bf16 splits (q pre-scaled 1/8)
  hmma_gemm<<<dim3(Pn / 128, Mrows / 128), 256, GEMM_SMEM>>>(b_in, nullptr, 0);
  // 2) Attention (HMMA flash) -> ctx bf16 splits
  attn_hmma<<<dim3(Tn / 128, BHn), 256, ATTN_SMEM>>>();
  // 3) Output projection (HMMA): M=4096, N=1024, K=1024
  hmma_gemm<<<dim3(En / 128, Mrows / 128), 256, GEMM_SMEM>>>(b_out, out, 1);
}

// round 7
// speedup vs baseline: 1.5443x; 1.5443x over previous
#include <cuda_runtime.h>
#include <cuda_bf16.h>
#include <math.h>
#include <cstdint>

// Problem dims (fixed by the reference)
#define Tn 2048
#define Bn 2
#define En 1024
#define Hn 16
#define Dn 64
#define BHn 32          // B*H
#define Pn 3072         // 3*E
#define Kdim 1024       // K of both GEMMs
#define Mrows 4096      // T*B

// ---------------------------------------------------------------------------
// Scratch: __device__ globals (allocation-free, graph-capturable)
// ---------------------------------------------------------------------------
__device__ __nv_bfloat16 gx_hi[(size_t)Mrows * Kdim];
__device__ __nv_bfloat16 gx_lo[(size_t)Mrows * Kdim];
__device__ __nv_bfloat16 gwin_hi[(size_t)Pn * Kdim];   // in_proj_w^T  [N][K]
__device__ __nv_bfloat16 gwin_lo[(size_t)Pn * Kdim];
__device__ __nv_bfloat16 gwout_hi[(size_t)En * Kdim];  // out_w^T      [N][K]
__device__ __nv_bfloat16 gwout_lo[(size_t)En * Kdim];
__device__ __nv_bfloat16 gctx_hi[(size_t)Mrows * Kdim];
__device__ __nv_bfloat16 gctx_lo[(size_t)Mrows * Kdim];
// q/k/v splits, layout [(b*H+h)][t][d]; q pre-scaled by 0.125
__device__ __nv_bfloat16 gq_hi[(size_t)BHn * Tn * Dn];
__device__ __nv_bfloat16 gq_lo[(size_t)BHn * Tn * Dn];
__device__ __nv_bfloat16 gk_hi[(size_t)BHn * Tn * Dn];
__device__ __nv_bfloat16 gk_lo[(size_t)BHn * Tn * Dn];
__device__ __nv_bfloat16 gv_hi[(size_t)BHn * Tn * Dn];
__device__ __nv_bfloat16 gv_lo[(size_t)BHn * Tn * Dn];

// ---------------------------------------------------------------------------
// PTX helpers (sm_103-safe: mma.sync + ldmatrix + cp.async only)
// ---------------------------------------------------------------------------
__device__ __forceinline__ uint32_t smem_u32(const void* p) {
  uint32_t a;
  asm("{ .reg .u64 t; cvta.to.shared.u64 t, %1; cvt.u32.u64 %0, t; }"
      : "=r"(a) : "l"(p));
  return a;
}

#define SW128(off) ((uint32_t)(off) ^ ((((uint32_t)(off)) >> 3) & 0x70))

#define CP_ASYNC16(dst, src)                                       \
  asm volatile("cp.async.cg.shared.global [%0], [%1], 16;"         \
               :: "r"(dst), "l"(src) : "memory")
#define CP_COMMIT() asm volatile("cp.async.commit_group;" ::: "memory")
#define CP_WAIT(n) asm volatile("cp.async.wait_group %0;" :: "n"(n) : "memory")

__device__ __forceinline__ void ldmx4(uint32_t* r, uint32_t addr) {
  asm volatile(
      "ldmatrix.sync.aligned.m8n8.x4.shared.b16 {%0,%1,%2,%3}, [%4];"
      : "=r"(r[0]), "=r"(r[1]), "=r"(r[2]), "=r"(r[3]) : "r"(addr));
}
__device__ __forceinline__ void ldmx4t(uint32_t* r, uint32_t addr) {
  asm volatile(
      "ldmatrix.sync.aligned.m8n8.x4.trans.shared.b16 {%0,%1,%2,%3}, [%4];"
      : "=r"(r[0]), "=r"(r[1]), "=r"(r[2]), "=r"(r[3]) : "r"(addr));
}

__device__ __forceinline__ void mma16816(float* c, const uint32_t* a,
                                         const uint32_t* b) {
  asm volatile(
      "mma.sync.aligned.m16n8k16.row.col.f32.bf16.bf16.f32 "
      "{%0,%1,%2,%3}, {%4,%5,%6,%7}, {%8,%9}, {%0,%1,%2,%3};"
      : "+f"(c[0]), "+f"(c[1]), "+f"(c[2]), "+f"(c[3])
      : "r"(a[0]), "r"(a[1]), "r"(a[2]), "r"(a[3]), "r"(b[0]), "r"(b[1]));
}

// split a float pair into bf16 hi/lo packed words
__device__ __forceinline__ void split2(float p0, float p1, uint32_t& h,
                                       uint32_t& l) {
  __nv_bfloat162 hh = __float22bfloat162_rn(make_float2(p0, p1));
  __nv_bfloat162 ll = __float22bfloat162_rn(
      make_float2(p0 - __bfloat162float(hh.x), p1 - __bfloat162float(hh.y)));
  h = *(uint32_t*)&hh;
  l = *(uint32_t*)&ll;
}

// ---------------------------------------------------------------------------
// Conversion kernels: fp32 -> bf16 hi/lo split
// ---------------------------------------------------------------------------
__global__ __launch_bounds__(256) void cvt_x(const float* __restrict__ xin) {
  size_t i = ((size_t)blockIdx.x * blockDim.x + threadIdx.x) * 4;
  if (i < (size_t)Mrows * Kdim) {
    float4 v = *(const float4*)(xin + i);
    __nv_bfloat16 h[4], l[4];
    h[0] = __float2bfloat16(v.x); l[0] = __float2bfloat16(v.x - __bfloat162float(h[0]));
    h[1] = __float2bfloat16(v.y); l[1] = __float2bfloat16(v.y - __bfloat162float(h[1]));
    h[2] = __float2bfloat16(v.z); l[2] = __float2bfloat16(v.z - __bfloat162float(h[2]));
    h[3] = __float2bfloat16(v.w); l[3] = __float2bfloat16(v.w - __bfloat162float(h[3]));
    *(uint2*)(gx_hi + i) = *(uint2*)h;
    *(uint2*)(gx_lo + i) = *(uint2*)l;
  }
}

// Transpose W[K][N] -> Wt_hi/lo [N][K] (bf16 split). which: 0=in_proj, 1=out
__global__ __launch_bounds__(256) void cvt_transpose(const float* __restrict__ W,
                                                     int which) {
  __nv_bfloat16* hi = (which == 0) ? gwin_hi : gwout_hi;
  __nv_bfloat16* lo = (which == 0) ? gwin_lo : gwout_lo;
  const int N = (which == 0) ? Pn : En;
  __shared__ float t[32][33];
  const int n0 = blockIdx.x * 32, k0 = blockIdx.y * 32;
  const int tx = threadIdx.x, ty = threadIdx.y;  // 32 x 8
#pragma unroll
  for (int i = ty; i < 32; i += 8)
    t[i][tx] = W[(size_t)(k0 + i) * N + n0 + tx];
  __syncthreads();
#pragma unroll
  for (int j = ty; j < 32; j += 8) {
    float v = t[tx][j];
    __nv_bfloat16 h = __float2bfloat16(v);
    __nv_bfloat16 l = __float2bfloat16(v - __bfloat162float(h));
    hi[(size_t)(n0 + j) * Kdim + k0 + tx] = h;
    lo[(size_t)(n0 + j) * Kdim + k0 + tx] = l;
  }
}

// ---------------------------------------------------------------------------
// HMMA split-bf16 GEMM: per CTA D[256 x 128] = A[M,K] * B^T[N,K] + bias
// BK=64, SW128, 96KB/stage double-buffered (192KB smem). 8 warps, 64x64 each.
//   mode 0: A = x split, B = in_proj^T; epilogue -> q/k/v bf16 splits
//   mode 1: A = ctx split, B = out_w^T; epilogue -> fp32 d_out
// ---------------------------------------------------------------------------
#define GOFF_AHI 0
#define GOFF_ALO 32768
#define GOFF_BHI 65536
#define GOFF_BLO 81920
#define GSTAGE 98304
#define GEMM_SMEM (2 * GSTAGE)  // 192 KB
#define NCHUNK (Kdim / 64)      // 16

// Load one BK=64 chunk: A 2048 vecs x2, B 1024 vecs x2 (16B each).
__device__ __forceinline__ void gemm_load_chunk(
    uint32_t sb, int kc, int tid,
    const __nv_bfloat16* __restrict__ Ahi, const __nv_bfloat16* __restrict__ Alo,
    const __nv_bfloat16* __restrict__ Bhi, const __nv_bfloat16* __restrict__ Blo,
    int m0, int n0) {
  const int k0 = kc * 64;
#pragma unroll
  for (int it = 0; it < 8; it++) {      // A: 256 rows x 8 segs
    const int v = tid + it * 256;
    const int row = v >> 3, seg = v & 7;
    const uint32_t sw = SW128(row * 128 + seg * 16);
    const size_t gi = (size_t)(m0 + row) * Kdim + k0 + seg * 8;
    CP_ASYNC16(sb + GOFF_AHI + sw, Ahi + gi);
    CP_ASYNC16(sb + GOFF_ALO + sw, Alo + gi);
  }
#pragma unroll
  for (int it = 0; it < 4; it++) {      // B: 128 rows x 8 segs
    const int v = tid + it * 256;
    const int row = v >> 3, seg = v & 7;
    const uint32_t sw = SW128(row * 128 + seg * 16);
    const size_t gi = (size_t)(n0 + row) * Kdim + k0 + seg * 8;
    CP_ASYNC16(sb + GOFF_BHI + sw, Bhi + gi);
    CP_ASYNC16(sb + GOFF_BLO + sw, Blo + gi);
  }
}

__global__ __launch_bounds__(256) void hmma_gemm(
    const float* __restrict__ bias, float* __restrict__ out, int mode) {
  extern __shared__ __align__(1024) char smc[];
  const uint32_t smem_base = smem_u32(smc);
  const int tid = threadIdx.x;
  const int wid = tid >> 5;
  const int lane = tid & 31;
  const int m0 = blockIdx.y * 256;
  const int n0 = blockIdx.x * 128;
  const int wm = (wid & 3) * 64;   // 4 warps along M
  const int wn = (wid >> 2) * 64;  // 2 warps along N

  const __nv_bfloat16* Ahi = (mode == 0) ? gx_hi : gctx_hi;
  const __nv_bfloat16* Alo = (mode == 0) ? gx_lo : gctx_lo;
  const __nv_bfloat16* Bhi = (mode == 0) ? gwin_hi : gwout_hi;
  const __nv_bfloat16* Blo = (mode == 0) ? gwin_lo : gwout_lo;

  float acc[4][8][4];
#pragma unroll
  for (int i = 0; i < 4; i++)
#pragma unroll
    for (int j = 0; j < 8; j++)
#pragma unroll
      for (int c = 0; c < 4; c++) acc[i][j][c] = 0.f;

  const int g = lane >> 3;
  const int rr = lane & 7;

  gemm_load_chunk(smem_base, 0, tid, Ahi, Alo, Bhi, Blo, m0, n0);
  CP_COMMIT();

  for (int c = 0; c < NCHUNK; c++) {
    const int buf = c & 1;
    if (c < NCHUNK - 1) {
      gemm_load_chunk(smem_base + (1 - buf) * GSTAGE, c + 1, tid, Ahi, Alo,
                      Bhi, Blo, m0, n0);
      CP_COMMIT();
      CP_WAIT(1);
    } else {
      CP_WAIT(0);
    }
    __syncthreads();

    const uint32_t sb = smem_base + buf * GSTAGE;
#pragma unroll
    for (int ks = 0; ks < 4; ks++) {
      uint32_t aH[4][4], aL[4][4], bH[4][4], bL[4][4];
#pragma unroll
      for (int i = 0; i < 4; i++) {
        int row = wm + i * 16 + (g & 1) * 8 + rr;
        uint32_t off = SW128(row * 128 + ks * 32 + (g >> 1) * 16);
        ldmx4(aH[i], sb + GOFF_AHI + off);
        ldmx4(aL[i], sb + GOFF_ALO + off);
      }
#pragma unroll
      for (int jj = 0; jj < 4; jj++) {
        int row = wn + jj * 16 + (g >> 1) * 8 + rr;
        uint32_t off = SW128(row * 128 + ks * 32 + (g & 1) * 16);
        ldmx4(bH[jj], sb + GOFF_BHI + off);
        ldmx4(bL[jj], sb + GOFF_BLO + off);
      }
#pragma unroll
      for (int i = 0; i < 4; i++)
#pragma unroll
        for (int j = 0; j < 8; j++) {
          const uint32_t* bh = &bH[j >> 1][(j & 1) * 2];
          const uint32_t* bl = &bL[j >> 1][(j & 1) * 2];
          mma16816(acc[i][j], aH[i], bh);
          mma16816(acc[i][j], aH[i], bl);
          mma16816(acc[i][j], aL[i], bh);
        }
    }
    __syncthreads();
  }

  // Epilogue
#pragma unroll
  for (int i = 0; i < 4; i++) {
#pragma unroll
    for (int j = 0; j < 8; j++) {
      const int mr = m0 + wm + i * 16 + (lane >> 2);
      const int f = n0 + wn + j * 8 + (lane & 3) * 2;
      const float b0 = bias[f], b1 = bias[f + 1];
      float p00 = acc[i][j][0] + b0, p01 = acc[i][j][1] + b1;
      float p10 = acc[i][j][2] + b0, p11 = acc[i][j][3] + b1;
      if (mode == 0) {
        const int which = f >> 10;
        const int h = (f & 1023) >> 6;
        const int d0 = f & 63;
        __nv_bfloat16 *dh, *dl;
        float scale = 1.f;
        if (which == 0) { dh = gq_hi; dl = gq_lo; scale = 0.125f; }
        else if (which == 1) { dh = gk_hi; dl = gk_lo; }
        else { dh = gv_hi; dl = gv_lo; }
        p00 *= scale; p01 *= scale; p10 *= scale; p11 *= scale;
        uint32_t h0, l0, h1, l1;
        split2(p00, p01, h0, l0);
        split2(p10, p11, h1, l1);
        const int t0 = mr >> 1, bb0 = mr & 1;
        const int t1 = (mr + 8) >> 1, bb1 = (mr + 8) & 1;
        size_t i0 = ((size_t)(bb0 * Hn + h) * Tn + t0) * Dn + d0;
        size_t i1 = ((size_t)(bb1 * Hn + h) * Tn + t1) * Dn + d0;
        *(uint32_t*)(dh + i0) = h0; *(uint32_t*)(dl + i0) = l0;
        *(uint32_t*)(dh + i1) = h1; *(uint32_t*)(dl + i1) = l1;
      } else {
        *(float2*)(out + (size_t)mr * En + f) = make_float2(p00, p01);
        *(float2*)(out + (size_t)(mr + 8) * En + f) = make_float2(p10, p11);
      }
    }
  }
}

// ---------------------------------------------------------------------------
// HMMA flash attention (round-4 version): per CTA 128 queries x 1 head;
// 8 warps x 16 rows. K/V 64-key chunks (hi/lo), double-buffered SW128 smem.
// ---------------------------------------------------------------------------
#define A_OFF_KHI 0
#define A_OFF_KLO 8192
#define A_OFF_VHI 16384
#define A_OFF_VLO 24576
#define A_STAGE 32768
#define A_OFF_QHI 65536
#define A_OFF_QLO 81920
#define ATTN_SMEM 98304

__device__ __forceinline__ void attn_load_chunk(uint32_t sb, int stg, int j0,
                                                int tid,
                                                const __nv_bfloat16* kh,
                                                const __nv_bfloat16* kl,
                                                const __nv_bfloat16* vh,
                                                const __nv_bfloat16* vl) {
  const uint32_t base = sb + stg * A_STAGE;
#pragma unroll
  for (int it = 0; it < 2; it++) {
    int vec = tid + it * 256;       // 0..511
    int r = vec >> 3, seg = vec & 7;
    uint32_t sw = SW128(r * 128 + seg * 16);
    size_t gi = ((size_t)(j0 + r)) * Dn + seg * 8;
    CP_ASYNC16(base + A_OFF_KHI + sw, kh + gi);
    CP_ASYNC16(base + A_OFF_KLO + sw, kl + gi);
    CP_ASYNC16(base + A_OFF_VHI + sw, vh + gi);
    CP_ASYNC16(base + A_OFF_VLO + sw, vl + gi);
  }
}

__global__ __launch_bounds__(256, 1) void attn_hmma() {
  extern __shared__ __align__(1024) char smc[];
  const uint32_t sb = smem_u32(smc);
  const int tid = threadIdx.x;
  const int wid = tid >> 5;
  const int lane = tid & 31;
  const int g = lane >> 3;
  const int rr = lane & 7;
  const int bh = blockIdx.y;
  const int q0 = blockIdx.x * 128;

  const __nv_bfloat16* qh = gq_hi + (size_t)bh * Tn * Dn;
  const __nv_bfloat16* ql = gq_lo + (size_t)bh * Tn * Dn;
  const __nv_bfloat16* kh = gk_hi + (size_t)bh * Tn * Dn;
  const __nv_bfloat16* kl = gk_lo + (size_t)bh * Tn * Dn;
  const __nv_bfloat16* vh = gv_hi + (size_t)bh * Tn * Dn;
  const __nv_bfloat16* vl = gv_lo + (size_t)bh * Tn * Dn;

  // Preamble: Q tile (hi/lo) + chunk 0, one commit group.
#pragma unroll
  for (int it = 0; it < 4; it++) {
    int vec = tid + it * 256;       // 0..1023
    int r = vec >> 3, seg = vec & 7;
    uint32_t sw = SW128(r * 128 + seg * 16);
    size_t gi = ((size_t)(q0 + r)) * Dn + seg * 8;
    CP_ASYNC16(sb + A_OFF_QHI + sw, qh + gi);
    CP_ASYNC16(sb + A_OFF_QLO + sw, ql + gi);
  }
  attn_load_chunk(sb, 0, 0, tid, kh, kl, vh, vl);
  CP_COMMIT();
  CP_WAIT(0);
  __syncthreads();

  // Q fragments held in registers for the whole key loop
  uint32_t qH[4][4], qL[4][4];
#pragma unroll
  for (int ks = 0; ks < 4; ks++) {
    int row = wid * 16 + (g & 1) * 8 + rr;
    uint32_t off = SW128(row * 128 + ks * 32 + (g >> 1) * 16);
    ldmx4(qH[ks], sb + A_OFF_QHI + off);
    ldmx4(qL[ks], sb + A_OFF_QLO + off);
  }

  float o[8][4];
#pragma unroll
  for (int dt = 0; dt < 8; dt++)
#pragma unroll
    for (int c = 0; c < 4; c++) o[dt][c] = 0.f;
  float m_i[2] = {-1e30f, -1e30f};
  float l_i[2] = {0.f, 0.f};

  for (int c = 0; c < 32; c++) {
    const int buf = c & 1;
    if (c < 31) {
      attn_load_chunk(sb, 1 - buf, (c + 1) * 64, tid, kh, kl, vh, vl);
      CP_COMMIT();
      CP_WAIT(1);
    } else {
      CP_WAIT(0);
    }
    __syncthreads();

    const uint32_t skh = sb + buf * A_STAGE + A_OFF_KHI;
    const uint32_t skl = sb + buf * A_STAGE + A_OFF_KLO;
    const uint32_t svh = sb + buf * A_STAGE + A_OFF_VHI;
    const uint32_t svl = sb + buf * A_STAGE + A_OFF_VLO;

    // ---- S = Q K^T (scaled: Q carries the 1/8) ----
    float s[8][4];
#pragma unroll
    for (int j = 0; j < 8; j++)
#pragma unroll
      for (int cc = 0; cc < 4; cc++) s[j][cc] = 0.f;

#pragma unroll
    for (int ks = 0; ks < 4; ks++) {
#pragma unroll
      for (int ng = 0; ng < 4; ng++) {
        uint32_t bkh[4], bkl[4];
        int row = ng * 16 + (g >> 1) * 8 + rr;
        uint32_t off = SW128(row * 128 + ks * 32 + (g & 1) * 16);
        ldmx4(bkh, skh + off);
        ldmx4(bkl, skl + off);
#pragma unroll
        for (int hf = 0; hf < 2; hf++) {
          const int j = ng * 2 + hf;
          mma16816(s[j], qH[ks], &bkh[hf * 2]);
          mma16816(s[j], qH[ks], &bkl[hf * 2]);
          mma16816(s[j], qL[ks], &bkh[hf * 2]);
        }
      }
    }

    // ---- online softmax (rows: l/4 and l/4+8) ----
#pragma unroll
    for (int r = 0; r < 2; r++) {
      float mx = -1e30f;
#pragma unroll
      for (int j = 0; j < 8; j++)
        mx = fmaxf(mx, fmaxf(s[j][2 * r], s[j][2 * r + 1]));
      mx = fmaxf(mx, __shfl_xor_sync(0xffffffffu, mx, 1));
      mx = fmaxf(mx, __shfl_xor_sync(0xffffffffu, mx, 2));
      float mnew = fmaxf(m_i[r], mx);
      float corr = __expf(m_i[r] - mnew);
      m_i[r] = mnew;
      float rs = 0.f;
#pragma unroll
      for (int j = 0; j < 8; j++) {
        float p0 = __expf(s[j][2 * r] - mnew);
        float p1 = __expf(s[j][2 * r + 1] - mnew);
        s[j][2 * r] = p0;
        s[j][2 * r + 1] = p1;
        rs += p0 + p1;
      }
      rs += __shfl_xor_sync(0xffffffffu, rs, 1);
      rs += __shfl_xor_sync(0xffffffffu, rs, 2);
      l_i[r] = l_i[r] * corr + rs;
#pragma unroll
      for (int dt = 0; dt < 8; dt++) {
        o[dt][2 * r] *= corr;
        o[dt][2 * r + 1] *= corr;
      }
    }

    // ---- O += P V ----
#pragma unroll
    for (int kk = 0; kk < 4; kk++) {
      uint32_t pH[4], pL[4];
      split2(s[2 * kk][0], s[2 * kk][1], pH[0], pL[0]);
      split2(s[2 * kk][2], s[2 * kk][3], pH[1], pL[1]);
      split2(s[2 * kk + 1][0], s[2 * kk + 1][1], pH[2], pL[2]);
      split2(s[2 * kk + 1][2], s[2 * kk + 1][3], pH[3], pL[3]);
#pragma unroll
      for (int dg = 0; dg < 4; dg++) {
        uint32_t bvh[4], bvl[4];
        int keyrow = kk * 16 + (g & 1) * 8 + rr;
        uint32_t off = SW128(keyrow * 128 + dg * 32 + (g >> 1) * 16);
        ldmx4t(bvh, svh + off);
        ldmx4t(bvl, svl + off);
#pragma unroll
        for (int hf = 0; hf < 2; hf++) {
          const int dt = dg * 2 + hf;
          mma16816(o[dt], pH, &bvh[hf * 2]);
          mma16816(o[dt], pH, &bvl[hf * 2]);
          mma16816(o[dt], pL, &bvh[hf * 2]);
        }
      }
    }
    __syncthreads();
  }

  // Epilogue: normalize, split to bf16 hi/lo, write scrambled ctx layout:
  //   ctx[b][h*128 + t/16][(t&15)*64 + d]
  const int b = bh >> 4;
  const int h = bh & 15;
#pragma unroll
  for (int r = 0; r < 2; r++) {
    const float inv = 1.0f / l_i[r];
    const int t = q0 + wid * 16 + (lane >> 2) + r * 8;
    const int row = h * 128 + (t >> 4);
    const size_t base = ((size_t)(b * Tn + row)) * En + ((t & 15) << 6);
#pragma unroll
    for (int dt = 0; dt < 8; dt++) {
      const int d = dt * 8 + (lane & 3) * 2;
      uint32_t hw, lw;
      split2(o[dt][2 * r] * inv, o[dt][2 * r + 1] * inv, hw, lw);
      *(uint32_t*)(gctx_hi + base + d) = hw;
      *(uint32_t*)(gctx_lo + base + d) = lw;
    }
  }
}

// ---------------------------------------------------------------------------
extern "C" void kernel_launch(void* const* d_in, const int* in_sizes, int n_in,
                              void* d_out, int out_size) {
  const float* x     = (const float*)d_in[0];  // (T, B, E)
  const float* w_in  = (const float*)d_in[1];  // (E, 3E)
  const float* b_in  = (const float*)d_in[2];  // (3E)
  const float* w_out = (const float*)d_in[3];  // (E, E)
  const float* b_out = (const float*)d_in[4];  // (E)
  float* out = (float*)d_out;                  // (B, T, E)

  cudaFuncSetAttribute(hmma_gemm, cudaFuncAttributeMaxDynamicSharedMemorySize,
                       GEMM_SMEM);
  cudaFuncSetAttribute(attn_hmma, cudaFuncAttributeMaxDynamicSharedMemorySize,
                       ATTN_SMEM);

  // bf16 split conversions
  cvt_x<<<(Mrows * Kdim / 4 + 255) / 256, 256>>>(x);
  cvt_transpose<<<dim3(Pn / 32, Kdim / 32), dim3(32, 8)>>>(w_in, 0);
  cvt_transpose<<<dim3(En / 32, Kdim / 32), dim3(32, 8)>>>(w_out, 1);

  // 1) QKV projection (HMMA) -> q/k/v bf16 splits (q pre-scaled 1/8)
  hmma_gemm<<<dim3(Pn / 128, Mrows / 256), 256, GEMM_SMEM>>>(b_in, nullptr, 0);
  // 2) Attention (HMMA flash) -> ctx bf16 splits
  attn_hmma<<<dim3(Tn / 128, BHn), 256, ATTN_SMEM>>>();
  // 3) Output projection (HMMA): M=4096, N=1024, K=1024
  hmma_gemm<<<dim3(En / 128, Mrows / 256), 256, GEMM_SMEM>>>(b_out, out, 1);
}

// round 9
// speedup vs baseline: 1.8376x; 1.1899x over previous
#include <cuda_runtime.h>
#include <cuda_bf16.h>
#include <cuda_fp16.h>
#include <math.h>
#include <cstdint>

// Problem dims (fixed by the reference)
#define Tn 2048
#define Bn 2
#define En 1024
#define Hn 16
#define Dn 64
#define BHn 32          // B*H
#define Pn 3072         // 3*E
#define Kdim 1024       // K of both GEMMs
#define Mrows 4096      // T*B

// ---------------------------------------------------------------------------
// Scratch: __device__ globals (allocation-free, graph-capturable)
// ---------------------------------------------------------------------------
__device__ __nv_bfloat16 gx_hi[(size_t)Mrows * Kdim];
__device__ __nv_bfloat16 gx_lo[(size_t)Mrows * Kdim];
__device__ __nv_bfloat16 gwin_hi[(size_t)Pn * Kdim];   // in_proj_w^T  [N][K]
__device__ __nv_bfloat16 gwin_lo[(size_t)Pn * Kdim];
__device__ __nv_bfloat16 gwout_hi[(size_t)En * Kdim];  // out_w^T      [N][K]
__device__ __nv_bfloat16 gwout_lo[(size_t)En * Kdim];
__device__ __nv_bfloat16 gctx_hi[(size_t)Mrows * Kdim];
__device__ __nv_bfloat16 gctx_lo[(size_t)Mrows * Kdim];
// attention operands in fp16, layout [(b*H+h)][t][d]; q pre-scaled by 0.125
__device__ __half gq_hi[(size_t)BHn * Tn * Dn];
__device__ __half gq_lo[(size_t)BHn * Tn * Dn];
__device__ __half gk_hi[(size_t)BHn * Tn * Dn];   // k: hi only (2-pass QK)
__device__ __half gv_hi[(size_t)BHn * Tn * Dn];
__device__ __half gv_lo[(size_t)BHn * Tn * Dn];

// ---------------------------------------------------------------------------
// PTX helpers (sm_103-safe: mma.sync + ldmatrix + cp.async only)
// ---------------------------------------------------------------------------
__device__ __forceinline__ uint32_t smem_u32(const void* p) {
  uint32_t a;
  asm("{ .reg .u64 t; cvta.to.shared.u64 t, %1; cvt.u32.u64 %0, t; }"
      : "=r"(a) : "l"(p));
  return a;
}

#define SW128(off) ((uint32_t)(off) ^ ((((uint32_t)(off)) >> 3) & 0x70))

#define CP_ASYNC16(dst, src)                                       \
  asm volatile("cp.async.cg.shared.global [%0], [%1], 16;"         \
               :: "r"(dst), "l"(src) : "memory")
#define CP_COMMIT() asm volatile("cp.async.commit_group;" ::: "memory")
#define CP_WAIT(n) asm volatile("cp.async.wait_group %0;" :: "n"(n) : "memory")

__device__ __forceinline__ void ldmx4(uint32_t* r, uint32_t addr) {
  asm volatile(
      "ldmatrix.sync.aligned.m8n8.x4.shared.b16 {%0,%1,%2,%3}, [%4];"
      : "=r"(r[0]), "=r"(r[1]), "=r"(r[2]), "=r"(r[3]) : "r"(addr));
}
__device__ __forceinline__ void ldmx4t(uint32_t* r, uint32_t addr) {
  asm volatile(
      "ldmatrix.sync.aligned.m8n8.x4.trans.shared.b16 {%0,%1,%2,%3}, [%4];"
      : "=r"(r[0]), "=r"(r[1]), "=r"(r[2]), "=r"(r[3]) : "r"(addr));
}

// bf16 MMA (projection GEMMs)
__device__ __forceinline__ void mma16816(float* c, const uint32_t* a,
                                         const uint32_t* b) {
  asm volatile(
      "mma.sync.aligned.m16n8k16.row.col.f32.bf16.bf16.f32 "
      "{%0,%1,%2,%3}, {%4,%5,%6,%7}, {%8,%9}, {%0,%1,%2,%3};"
      : "+f"(c[0]), "+f"(c[1]), "+f"(c[2]), "+f"(c[3])
      : "r"(a[0]), "r"(a[1]), "r"(a[2]), "r"(a[3]), "r"(b[0]), "r"(b[1]));
}
// fp16 MMA (attention)
__device__ __forceinline__ void mma16816h(float* c, const uint32_t* a,
                                          const uint32_t* b) {
  asm volatile(
      "mma.sync.aligned.m16n8k16.row.col.f32.f16.f16.f32 "
      "{%0,%1,%2,%3}, {%4,%5,%6,%7}, {%8,%9}, {%0,%1,%2,%3};"
      : "+f"(c[0]), "+f"(c[1]), "+f"(c[2]), "+f"(c[3])
      : "r"(a[0]), "r"(a[1]), "r"(a[2]), "r"(a[3]), "r"(b[0]), "r"(b[1]));
}

// split a float pair into bf16 hi/lo packed words
__device__ __forceinline__ void split2(float p0, float p1, uint32_t& h,
                                       uint32_t& l) {
  __nv_bfloat162 hh = __float22bfloat162_rn(make_float2(p0, p1));
  __nv_bfloat162 ll = __float22bfloat162_rn(
      make_float2(p0 - __bfloat162float(hh.x), p1 - __bfloat162float(hh.y)));
  h = *(uint32_t*)&hh;
  l = *(uint32_t*)&ll;
}

// split a float pair into fp16 hi/lo packed words
__device__ __forceinline__ void split2h(float p0, float p1, uint32_t& h,
                                        uint32_t& l) {
  __half2 hh = __float22half2_rn(make_float2(p0, p1));
  float r0 = p0 - __half2float(__low2half(hh));
  float r1 = p1 - __half2float(__high2half(hh));
  __half2 ll = __float22half2_rn(make_float2(r0, r1));
  h = *(uint32_t*)&hh;
  l = *(uint32_t*)&ll;
}
__device__ __forceinline__ uint32_t cvt2h(float p0, float p1) {
  __half2 hh = __float22half2_rn(make_float2(p0, p1));
  return *(uint32_t*)&hh;
}

// ---------------------------------------------------------------------------
// Conversion kernels: fp32 -> bf16 hi/lo split
// ---------------------------------------------------------------------------
__global__ __launch_bounds__(256) void cvt_x(const float* __restrict__ xin) {
  size_t i = ((size_t)blockIdx.x * blockDim.x + threadIdx.x) * 4;
  if (i < (size_t)Mrows * Kdim) {
    float4 v = *(const float4*)(xin + i);
    __nv_bfloat16 h[4], l[4];
    h[0] = __float2bfloat16(v.x); l[0] = __float2bfloat16(v.x - __bfloat162float(h[0]));
    h[1] = __float2bfloat16(v.y); l[1] = __float2bfloat16(v.y - __bfloat162float(h[1]));
    h[2] = __float2bfloat16(v.z); l[2] = __float2bfloat16(v.z - __bfloat162float(h[2]));
    h[3] = __float2bfloat16(v.w); l[3] = __float2bfloat16(v.w - __bfloat162float(h[3]));
    *(uint2*)(gx_hi + i) = *(uint2*)h;
    *(uint2*)(gx_lo + i) = *(uint2*)l;
  }
}

// Transpose W[K][N] -> Wt_hi/lo [N][K] (bf16 split). which: 0=in_proj, 1=out
__global__ __launch_bounds__(256) void cvt_transpose(const float* __restrict__ W,
                                                     int which) {
  __nv_bfloat16* hi = (which == 0) ? gwin_hi : gwout_hi;
  __nv_bfloat16* lo = (which == 0) ? gwin_lo : gwout_lo;
  const int N = (which == 0) ? Pn : En;
  __shared__ float t[32][33];
  const int n0 = blockIdx.x * 32, k0 = blockIdx.y * 32;
  const int tx = threadIdx.x, ty = threadIdx.y;  // 32 x 8
#pragma unroll
  for (int i = ty; i < 32; i += 8)
    t[i][tx] = W[(size_t)(k0 + i) * N + n0 + tx];
  __syncthreads();
#pragma unroll
  for (int j = ty; j < 32; j += 8) {
    float v = t[tx][j];
    __nv_bfloat16 h = __float2bfloat16(v);
    __nv_bfloat16 l = __float2bfloat16(v - __bfloat162float(h));
    hi[(size_t)(n0 + j) * Kdim + k0 + tx] = h;
    lo[(size_t)(n0 + j) * Kdim + k0 + tx] = l;
  }
}

// ---------------------------------------------------------------------------
// HMMA split-bf16 GEMM: per CTA D[256 x 128] = A[M,K] * B^T[N,K] + bias
// BK=64, SW128, 96KB/stage double-buffered (192KB smem). 8 warps, 64x64 each.
//   mode 0: A = x split, B = in_proj^T; epilogue -> q/k/v fp16 (q scaled 1/8)
//   mode 1: A = ctx split, B = out_w^T; epilogue -> fp32 d_out
// ---------------------------------------------------------------------------
#define GOFF_AHI 0
#define GOFF_ALO 32768
#define GOFF_BHI 65536
#define GOFF_BLO 81920
#define GSTAGE 98304
#define GEMM_SMEM (2 * GSTAGE)  // 192 KB
#define NCHUNK (Kdim / 64)      // 16

__device__ __forceinline__ void gemm_load_chunk(
    uint32_t sb, int kc, int tid,
    const __nv_bfloat16* __restrict__ Ahi, const __nv_bfloat16* __restrict__ Alo,
    const __nv_bfloat16* __restrict__ Bhi, const __nv_bfloat16* __restrict__ Blo,
    int m0, int n0) {
  const int k0 = kc * 64;
#pragma unroll
  for (int it = 0; it < 8; it++) {      // A: 256 rows x 8 segs
    const int v = tid + it * 256;
    const int row = v >> 3, seg = v & 7;
    const uint32_t sw = SW128(row * 128 + seg * 16);
    const size_t gi = (size_t)(m0 + row) * Kdim + k0 + seg * 8;
    CP_ASYNC16(sb + GOFF_AHI + sw, Ahi + gi);
    CP_ASYNC16(sb + GOFF_ALO + sw, Alo + gi);
  }
#pragma unroll
  for (int it = 0; it < 4; it++) {      // B: 128 rows x 8 segs
    const int v = tid + it * 256;
    const int row = v >> 3, seg = v & 7;
    const uint32_t sw = SW128(row * 128 + seg * 16);
    const size_t gi = (size_t)(n0 + row) * Kdim + k0 + seg * 8;
    CP_ASYNC16(sb + GOFF_BHI + sw, Bhi + gi);
    CP_ASYNC16(sb + GOFF_BLO + sw, Blo + gi);
  }
}

__global__ __launch_bounds__(256) void hmma_gemm(
    const float* __restrict__ bias, float* __restrict__ out, int mode) {
  extern __shared__ __align__(1024) char smc[];
  const uint32_t smem_base = smem_u32(smc);
  const int tid = threadIdx.x;
  const int wid = tid >> 5;
  const int lane = tid & 31;
  const int m0 = blockIdx.y * 256;
  const int n0 = blockIdx.x * 128;
  const int wm = (wid & 3) * 64;   // 4 warps along M
  const int wn = (wid >> 2) * 64;  // 2 warps along N

  const __nv_bfloat16* Ahi = (mode == 0) ? gx_hi : gctx_hi;
  const __nv_bfloat16* Alo = (mode == 0) ? gx_lo : gctx_lo;
  const __nv_bfloat16* Bhi = (mode == 0) ? gwin_hi : gwout_hi;
  const __nv_bfloat16* Blo = (mode == 0) ? gwin_lo : gwout_lo;

  float acc[4][8][4];
#pragma unroll
  for (int i = 0; i < 4; i++)
#pragma unroll
    for (int j = 0; j < 8; j++)
#pragma unroll
      for (int c = 0; c < 4; c++) acc[i][j][c] = 0.f;

  const int g = lane >> 3;
  const int rr = lane & 7;

  gemm_load_chunk(smem_base, 0, tid, Ahi, Alo, Bhi, Blo, m0, n0);
  CP_COMMIT();

  for (int c = 0; c < NCHUNK; c++) {
    const int buf = c & 1;
    if (c < NCHUNK - 1) {
      gemm_load_chunk(smem_base + (1 - buf) * GSTAGE, c + 1, tid, Ahi, Alo,
                      Bhi, Blo, m0, n0);
      CP_COMMIT();
      CP_WAIT(1);
    } else {
      CP_WAIT(0);
    }
    __syncthreads();

    const uint32_t sb = smem_base + buf * GSTAGE;
#pragma unroll
    for (int ks = 0; ks < 4; ks++) {
      uint32_t aH[4][4], aL[4][4], bH[4][4], bL[4][4];
#pragma unroll
      for (int i = 0; i < 4; i++) {
        int row = wm + i * 16 + (g & 1) * 8 + rr;
        uint32_t off = SW128(row * 128 + ks * 32 + (g >> 1) * 16);
        ldmx4(aH[i], sb + GOFF_AHI + off);
        ldmx4(aL[i], sb + GOFF_ALO + off);
      }
#pragma unroll
      for (int jj = 0; jj < 4; jj++) {
        int row = wn + jj * 16 + (g >> 1) * 8 + rr;
        uint32_t off = SW128(row * 128 + ks * 32 + (g & 1) * 16);
        ldmx4(bH[jj], sb + GOFF_BHI + off);
        ldmx4(bL[jj], sb + GOFF_BLO + off);
      }
#pragma unroll
      for (int i = 0; i < 4; i++)
#pragma unroll
        for (int j = 0; j < 8; j++) {
          const uint32_t* bh = &bH[j >> 1][(j & 1) * 2];
          const uint32_t* bl = &bL[j >> 1][(j & 1) * 2];
          mma16816(acc[i][j], aH[i], bh);
          mma16816(acc[i][j], aH[i], bl);
          mma16816(acc[i][j], aL[i], bh);
        }
    }
    __syncthreads();
  }

  // Epilogue
#pragma unroll
  for (int i = 0; i < 4; i++) {
#pragma unroll
    for (int j = 0; j < 8; j++) {
      const int mr = m0 + wm + i * 16 + (lane >> 2);
      const int f = n0 + wn + j * 8 + (lane & 3) * 2;
      const float b0 = bias[f], b1 = bias[f + 1];
      float p00 = acc[i][j][0] + b0, p01 = acc[i][j][1] + b1;
      float p10 = acc[i][j][2] + b0, p11 = acc[i][j][3] + b1;
      if (mode == 0) {
        const int which = f >> 10;
        const int h = (f & 1023) >> 6;
        const int d0 = f & 63;
        const int t0 = mr >> 1, bb0 = mr & 1;
        const int t1 = (mr + 8) >> 1, bb1 = (mr + 8) & 1;
        size_t i0 = ((size_t)(bb0 * Hn + h) * Tn + t0) * Dn + d0;
        size_t i1 = ((size_t)(bb1 * Hn + h) * Tn + t1) * Dn + d0;
        if (which == 0) {        // q: fp16 hi/lo, pre-scaled by 1/8
          uint32_t h0, l0, h1, l1;
          split2h(p00 * 0.125f, p01 * 0.125f, h0, l0);
          split2h(p10 * 0.125f, p11 * 0.125f, h1, l1);
          *(uint32_t*)(gq_hi + i0) = h0; *(uint32_t*)(gq_lo + i0) = l0;
          *(uint32_t*)(gq_hi + i1) = h1; *(uint32_t*)(gq_lo + i1) = l1;
        } else if (which == 1) { // k: fp16 hi only
          *(uint32_t*)(gk_hi + i0) = cvt2h(p00, p01);
          *(uint32_t*)(gk_hi + i1) = cvt2h(p10, p11);
        } else {                 // v: fp16 hi/lo
          uint32_t h0, l0, h1, l1;
          split2h(p00, p01, h0, l0);
          split2h(p10, p11, h1, l1);
          *(uint32_t*)(gv_hi + i0) = h0; *(uint32_t*)(gv_lo + i0) = l0;
          *(uint32_t*)(gv_hi + i1) = h1; *(uint32_t*)(gv_lo + i1) = l1;
        }
      } else {
        *(float2*)(out + (size_t)mr * En + f) = make_float2(p00, p01);
        *(float2*)(out + (size_t)(mr + 8) * En + f) = make_float2(p10, p11);
      }
    }
  }
}

// ---------------------------------------------------------------------------
// fp16 HMMA flash attention: per CTA 128 queries x 1 head; 8 warps x 16 rows.
// 2-pass QK (qH*kH + qL*kH; k hi-only) and 2-pass PV (pH*vH + pH*vL).
// K/V 64-key chunks, double-buffered cp.async SW128 smem (24KB/stage).
// Q hi/lo tiles are 16KB each (128 rows x 128B).
// ---------------------------------------------------------------------------
#define A_OFF_KHI 0
#define A_OFF_VHI 8192
#define A_OFF_VLO 16384
#define A_STAGE 24576
#define A_OFF_QHI (2 * A_STAGE)            // 49152
#define A_OFF_QLO (2 * A_STAGE + 16384)    // 65536
#define ATTN_SMEM (2 * A_STAGE + 32768)    // 81920

__device__ __forceinline__ void attn_load_chunk(uint32_t sb, int stg, int j0,
                                                int tid,
                                                const __half* kh,
                                                const __half* vh,
                                                const __half* vl) {
  const uint32_t base = sb + stg * A_STAGE;
#pragma unroll
  for (int it = 0; it < 2; it++) {
    int vec = tid + it * 256;       // 0..511
    int r = vec >> 3, seg = vec & 7;
    uint32_t sw = SW128(r * 128 + seg * 16);
    size_t gi = ((size_t)(j0 + r)) * Dn + seg * 8;
    CP_ASYNC16(base + A_OFF_KHI + sw, kh + gi);
    CP_ASYNC16(base + A_OFF_VHI + sw, vh + gi);
    CP_ASYNC16(base + A_OFF_VLO + sw, vl + gi);
  }
}

__global__ __launch_bounds__(256, 1) void attn_hmma() {
  extern __shared__ __align__(1024) char smc[];
  const uint32_t sb = smem_u32(smc);
  const int tid = threadIdx.x;
  const int wid = tid >> 5;
  const int lane = tid & 31;
  const int g = lane >> 3;
  const int rr = lane & 7;
  const int bh = blockIdx.y;
  const int q0 = blockIdx.x * 128;

  const __half* qh = gq_hi + (size_t)bh * Tn * Dn;
  const __half* ql = gq_lo + (size_t)bh * Tn * Dn;
  const __half* kh = gk_hi + (size_t)bh * Tn * Dn;
  const __half* vh = gv_hi + (size_t)bh * Tn * Dn;
  const __half* vl = gv_lo + (size_t)bh * Tn * Dn;

  // Preamble: Q tile (hi/lo) + chunk 0, one commit group.
#pragma unroll
  for (int it = 0; it < 4; it++) {
    int vec = tid + it * 256;       // 0..1023
    int r = vec >> 3, seg = vec & 7;
    uint32_t sw = SW128(r * 128 + seg * 16);
    size_t gi = ((size_t)(q0 + r)) * Dn + seg * 8;
    CP_ASYNC16(sb + A_OFF_QHI + sw, qh + gi);
    CP_ASYNC16(sb + A_OFF_QLO + sw, ql + gi);
  }
  attn_load_chunk(sb, 0, 0, tid, kh, vh, vl);
  CP_COMMIT();
  CP_WAIT(0);
  __syncthreads();

  // Q fragments held in registers for the whole key loop
  uint32_t qH[4][4], qL[4][4];
#pragma unroll
  for (int ks = 0; ks < 4; ks++) {
    int row = wid * 16 + (g & 1) * 8 + rr;
    uint32_t off = SW128(row * 128 + ks * 32 + (g >> 1) * 16);
    ldmx4(qH[ks], sb + A_OFF_QHI + off);
    ldmx4(qL[ks], sb + A_OFF_QLO + off);
  }

  float o[8][4];
#pragma unroll
  for (int dt = 0; dt < 8; dt++)
#pragma unroll
    for (int c = 0; c < 4; c++) o[dt][c] = 0.f;
  float m_i[2] = {-1e30f, -1e30f};
  float l_i[2] = {0.f, 0.f};

  for (int c = 0; c < 32; c++) {
    const int buf = c & 1;
    if (c < 31) {
      attn_load_chunk(sb, 1 - buf, (c + 1) * 64, tid, kh, vh, vl);
      CP_COMMIT();
      CP_WAIT(1);
    } else {
      CP_WAIT(0);
    }
    __syncthreads();

    const uint32_t skh = sb + buf * A_STAGE + A_OFF_KHI;
    const uint32_t svh = sb + buf * A_STAGE + A_OFF_VHI;
    const uint32_t svl = sb + buf * A_STAGE + A_OFF_VLO;

    // ---- S = Q K^T (scaled: Q carries the 1/8); k hi-only, q corrected ----
    float s[8][4];
#pragma unroll
    for (int j = 0; j < 8; j++)
#pragma unroll
      for (int cc = 0; cc < 4; cc++) s[j][cc] = 0.f;

#pragma unroll
    for (int ks = 0; ks < 4; ks++) {
#pragma unroll
      for (int ng = 0; ng < 4; ng++) {
        uint32_t bkh[4];
        int row = ng * 16 + (g >> 1) * 8 + rr;
        uint32_t off = SW128(row * 128 + ks * 32 + (g & 1) * 16);
        ldmx4(bkh, skh + off);
#pragma unroll
        for (int hf = 0; hf < 2; hf++) {
          const int j = ng * 2 + hf;
          mma16816h(s[j], qH[ks], &bkh[hf * 2]);
          mma16816h(s[j], qL[ks], &bkh[hf * 2]);
        }
      }
    }

    // ---- online softmax (rows: l/4 and l/4+8) ----
#pragma unroll
    for (int r = 0; r < 2; r++) {
      float mx = -1e30f;
#pragma unroll
      for (int j = 0; j < 8; j++)
        mx = fmaxf(mx, fmaxf(s[j][2 * r], s[j][2 * r + 1]));
      mx = fmaxf(mx, __shfl_xor_sync(0xffffffffu, mx, 1));
      mx = fmaxf(mx, __shfl_xor_sync(0xffffffffu, mx, 2));
      float mnew = fmaxf(m_i[r], mx);
      float corr = __expf(m_i[r] - mnew);
      m_i[r] = mnew;
      float rs = 0.f;
#pragma unroll
      for (int j = 0; j < 8; j++) {
        float p0 = __expf(s[j][2 * r] - mnew);
        float p1 = __expf(s[j][2 * r + 1] - mnew);
        s[j][2 * r] = p0;
        s[j][2 * r + 1] = p1;
        rs += p0 + p1;
      }
      rs += __shfl_xor_sync(0xffffffffu, rs, 1);
      rs += __shfl_xor_sync(0xffffffffu, rs, 2);
      l_i[r] = l_i[r] * corr + rs;
#pragma unroll
      for (int dt = 0; dt < 8; dt++) {
        o[dt][2 * r] *= corr;
        o[dt][2 * r + 1] *= corr;
      }
    }

    // ---- O += P V (P single fp16; v hi+lo corrected) ----
#pragma unroll
    for (int kk = 0; kk < 4; kk++) {
      uint32_t pH[4];
      pH[0] = cvt2h(s[2 * kk][0], s[2 * kk][1]);
      pH[1] = cvt2h(s[2 * kk][2], s[2 * kk][3]);
      pH[2] = cvt2h(s[2 * kk + 1][0], s[2 * kk + 1][1]);
      pH[3] = cvt2h(s[2 * kk + 1][2], s[2 * kk + 1][3]);
#pragma unroll
      for (int dg = 0; dg < 4; dg++) {
        uint32_t bvh[4], bvl[4];
        int keyrow = kk * 16 + (g & 1) * 8 + rr;
        uint32_t off = SW128(keyrow * 128 + dg * 32 + (g >> 1) * 16);
        ldmx4t(bvh, svh + off);
        ldmx4t(bvl, svl + off);
#pragma unroll
        for (int hf = 0; hf < 2; hf++) {
          const int dt = dg * 2 + hf;
          mma16816h(o[dt], pH, &bvh[hf * 2]);
          mma16816h(o[dt], pH, &bvl[hf * 2]);
        }
      }
    }
    __syncthreads();
  }

  // Epilogue: normalize, split to bf16 hi/lo, write scrambled ctx layout:
  //   ctx[b][h*128 + t/16][(t&15)*64 + d]
  const int b = bh >> 4;
  const int h = bh & 15;
#pragma unroll
  for (int r = 0; r < 2; r++) {
    const float inv = 1.0f / l_i[r];
    const int t = q0 + wid * 16 + (lane >> 2) + r * 8;
    const int row = h * 128 + (t >> 4);
    const size_t base = ((size_t)(b * Tn + row)) * En + ((t & 15) << 6);
#pragma unroll
    for (int dt = 0; dt < 8; dt++) {
      const int d = dt * 8 + (lane & 3) * 2;
      uint32_t hw, lw;
      split2(o[dt][2 * r] * inv, o[dt][2 * r + 1] * inv, hw, lw);
      *(uint32_t*)(gctx_hi + base + d) = hw;
      *(uint32_t*)(gctx_lo + base + d) = lw;
    }
  }
}

// ---------------------------------------------------------------------------
extern "C" void kernel_launch(void* const* d_in, const int* in_sizes, int n_in,
                              void* d_out, int out_size) {
  const float* x     = (const float*)d_in[0];  // (T, B, E)
  const float* w_in  = (const float*)d_in[1];  // (E, 3E)
  const float* b_in  = (const float*)d_in[2];  // (3E)
  const float* w_out = (const float*)d_in[3];  // (E, E)
  const float* b_out = (const float*)d_in[4];  // (E)
  float* out = (float*)d_out;                  // (B, T, E)

  cudaFuncSetAttribute(hmma_gemm, cudaFuncAttributeMaxDynamicSharedMemorySize,
                       GEMM_SMEM);
  cudaFuncSetAttribute(attn_hmma, cudaFuncAttributeMaxDynamicSharedMemorySize,
                       ATTN_SMEM);

  // bf16 split conversions
  cvt_x<<<(Mrows * Kdim / 4 + 255) / 256, 256>>>(x);
  cvt_transpose<<<dim3(Pn / 32, Kdim / 32), dim3(32, 8)>>>(w_in, 0);
  cvt_transpose<<<dim3(En / 32, Kdim / 32), dim3(32, 8)>>>(w_out, 1);

  // 1) QKV projection (HMMA bf16 split) -> q/k/v fp16 (q pre-scaled 1/8)
  hmma_gemm<<<dim3(Pn / 128, Mrows / 256), 256, GEMM_SMEM>>>(b_in, nullptr, 0);
  // 2) Attention (fp16 HMMA flash, 2-pass QK/PV) -> ctx bf16 splits
  attn_hmma<<<dim3(Tn / 128, BHn), 256, ATTN_SMEM>>>();
  // 3) Output projection (HMMA bf16 split): M=4096, N=1024, K=1024
  hmma_gemm<<<dim3(En / 128, Mrows / 256), 256, GEMM_SMEM>>>(b_out, out, 1);
}

// round 10
// speedup vs baseline: 2.1916x; 1.1926x over previous
#include <cuda_runtime.h>
#include <cuda_bf16.h>
#include <cuda_fp16.h>
#include <math.h>
#include <cstdint>

// Problem dims (fixed by the reference)
#define Tn 2048
#define Bn 2
#define En 1024
#define Hn 16
#define Dn 64
#define BHn 32          // B*H
#define Pn 3072         // 3*E
#define Kdim 1024       // K of both GEMMs
#define Mrows 4096      // T*B

// ---------------------------------------------------------------------------
// Scratch: __device__ globals (allocation-free, graph-capturable)
// All operands fp16: activations split hi/lo, weights hi-only.
// ---------------------------------------------------------------------------
__device__ __half gx_hi[(size_t)Mrows * Kdim];
__device__ __half gx_lo[(size_t)Mrows * Kdim];
__device__ __half gwin_hi[(size_t)Pn * Kdim];   // in_proj_w^T [N][K], hi only
__device__ __half gwout_hi[(size_t)En * Kdim];  // out_w^T     [N][K], hi only
__device__ __half gctx_hi[(size_t)Mrows * Kdim];
__device__ __half gctx_lo[(size_t)Mrows * Kdim];
// attention operands, layout [(b*H+h)][t][d]; q pre-scaled by 0.125
__device__ __half gq_hi[(size_t)BHn * Tn * Dn];
__device__ __half gq_lo[(size_t)BHn * Tn * Dn];
__device__ __half gk_hi[(size_t)BHn * Tn * Dn];   // k: hi only
__device__ __half gv_hi[(size_t)BHn * Tn * Dn];
__device__ __half gv_lo[(size_t)BHn * Tn * Dn];

// ---------------------------------------------------------------------------
// PTX helpers (sm_103-safe: mma.sync + ldmatrix + cp.async only)
// ---------------------------------------------------------------------------
__device__ __forceinline__ uint32_t smem_u32(const void* p) {
  uint32_t a;
  asm("{ .reg .u64 t; cvta.to.shared.u64 t, %1; cvt.u32.u64 %0, t; }"
      : "=r"(a) : "l"(p));
  return a;
}

#define SW128(off) ((uint32_t)(off) ^ ((((uint32_t)(off)) >> 3) & 0x70))

#define CP_ASYNC16(dst, src)                                       \
  asm volatile("cp.async.cg.shared.global [%0], [%1], 16;"         \
               :: "r"(dst), "l"(src) : "memory")
#define CP_COMMIT() asm volatile("cp.async.commit_group;" ::: "memory")
#define CP_WAIT(n) asm volatile("cp.async.wait_group %0;" :: "n"(n) : "memory")

__device__ __forceinline__ void ldmx4(uint32_t* r, uint32_t addr) {
  asm volatile(
      "ldmatrix.sync.aligned.m8n8.x4.shared.b16 {%0,%1,%2,%3}, [%4];"
      : "=r"(r[0]), "=r"(r[1]), "=r"(r[2]), "=r"(r[3]) : "r"(addr));
}
__device__ __forceinline__ void ldmx4t(uint32_t* r, uint32_t addr) {
  asm volatile(
      "ldmatrix.sync.aligned.m8n8.x4.trans.shared.b16 {%0,%1,%2,%3}, [%4];"
      : "=r"(r[0]), "=r"(r[1]), "=r"(r[2]), "=r"(r[3]) : "r"(addr));
}

// fp16 MMA (everything)
__device__ __forceinline__ void mma16816h(float* c, const uint32_t* a,
                                          const uint32_t* b) {
  asm volatile(
      "mma.sync.aligned.m16n8k16.row.col.f32.f16.f16.f32 "
      "{%0,%1,%2,%3}, {%4,%5,%6,%7}, {%8,%9}, {%0,%1,%2,%3};"
      : "+f"(c[0]), "+f"(c[1]), "+f"(c[2]), "+f"(c[3])
      : "r"(a[0]), "r"(a[1]), "r"(a[2]), "r"(a[3]), "r"(b[0]), "r"(b[1]));
}

// split a float pair into fp16 hi/lo packed words
__device__ __forceinline__ void split2h(float p0, float p1, uint32_t& h,
                                        uint32_t& l) {
  __half2 hh = __float22half2_rn(make_float2(p0, p1));
  float r0 = p0 - __half2float(__low2half(hh));
  float r1 = p1 - __half2float(__high2half(hh));
  __half2 ll = __float22half2_rn(make_float2(r0, r1));
  h = *(uint32_t*)&hh;
  l = *(uint32_t*)&ll;
}
__device__ __forceinline__ uint32_t cvt2h(float p0, float p1) {
  __half2 hh = __float22half2_rn(make_float2(p0, p1));
  return *(uint32_t*)&hh;
}

// ---------------------------------------------------------------------------
// Conversion kernels: fp32 -> fp16 hi/lo split
// ---------------------------------------------------------------------------
__global__ __launch_bounds__(256) void cvt_x(const float* __restrict__ xin) {
  size_t i = ((size_t)blockIdx.x * blockDim.x + threadIdx.x) * 4;
  if (i < (size_t)Mrows * Kdim) {
    float4 v = *(const float4*)(xin + i);
    uint32_t h0, l0, h1, l1;
    split2h(v.x, v.y, h0, l0);
    split2h(v.z, v.w, h1, l1);
    uint2 hw = make_uint2(h0, h1), lw = make_uint2(l0, l1);
    *(uint2*)(gx_hi + i) = hw;
    *(uint2*)(gx_lo + i) = lw;
  }
}

// Transpose W[K][N] -> Wt_hi [N][K] (fp16 hi only). which: 0=in_proj, 1=out
__global__ __launch_bounds__(256) void cvt_transpose(const float* __restrict__ W,
                                                     int which) {
  __half* hi = (which == 0) ? gwin_hi : gwout_hi;
  const int N = (which == 0) ? Pn : En;
  __shared__ float t[32][33];
  const int n0 = blockIdx.x * 32, k0 = blockIdx.y * 32;
  const int tx = threadIdx.x, ty = threadIdx.y;  // 32 x 8
#pragma unroll
  for (int i = ty; i < 32; i += 8)
    t[i][tx] = W[(size_t)(k0 + i) * N + n0 + tx];
  __syncthreads();
#pragma unroll
  for (int j = ty; j < 32; j += 8)
    hi[(size_t)(n0 + j) * Kdim + k0 + tx] = __float2half(t[tx][j]);
}

// ---------------------------------------------------------------------------
// fp16 HMMA GEMM: per CTA D[256 x 128] = A[M,K] * B^T[N,K] + bias
// A fully corrected (hi/lo), B hi-only: 2-pass aH*bH + aL*bH.
// BK=64, SW128, 80KB/stage double-buffered (160KB smem). 8 warps, 64x64 each.
//   mode 0: A = x split, B = in_proj^T; epilogue -> q/k/v fp16 (q scaled 1/8)
//   mode 1: A = ctx split, B = out_w^T; epilogue -> fp32 d_out
// ---------------------------------------------------------------------------
#define GOFF_AHI 0
#define GOFF_ALO 32768
#define GOFF_BHI 65536
#define GSTAGE 81920
#define GEMM_SMEM (2 * GSTAGE)  // 160 KB
#define NCHUNK (Kdim / 64)      // 16

__device__ __forceinline__ void gemm_load_chunk(
    uint32_t sb, int kc, int tid,
    const __half* __restrict__ Ahi, const __half* __restrict__ Alo,
    const __half* __restrict__ Bhi, int m0, int n0) {
  const int k0 = kc * 64;
#pragma unroll
  for (int it = 0; it < 8; it++) {      // A: 256 rows x 8 segs of 16B
    const int v = tid + it * 256;
    const int row = v >> 3, seg = v & 7;
    const uint32_t sw = SW128(row * 128 + seg * 16);
    const size_t gi = (size_t)(m0 + row) * Kdim + k0 + seg * 8;
    CP_ASYNC16(sb + GOFF_AHI + sw, Ahi + gi);
    CP_ASYNC16(sb + GOFF_ALO + sw, Alo + gi);
  }
#pragma unroll
  for (int it = 0; it < 4; it++) {      // B: 128 rows x 8 segs of 16B
    const int v = tid + it * 256;
    const int row = v >> 3, seg = v & 7;
    const uint32_t sw = SW128(row * 128 + seg * 16);
    const size_t gi = (size_t)(n0 + row) * Kdim + k0 + seg * 8;
    CP_ASYNC16(sb + GOFF_BHI + sw, Bhi + gi);
  }
}

__global__ __launch_bounds__(256) void hmma_gemm(
    const float* __restrict__ bias, float* __restrict__ out, int mode) {
  extern __shared__ __align__(1024) char smc[];
  const uint32_t smem_base = smem_u32(smc);
  const int tid = threadIdx.x;
  const int wid = tid >> 5;
  const int lane = tid & 31;
  const int m0 = blockIdx.y * 256;
  const int n0 = blockIdx.x * 128;
  const int wm = (wid & 3) * 64;   // 4 warps along M
  const int wn = (wid >> 2) * 64;  // 2 warps along N

  const __half* Ahi = (mode == 0) ? gx_hi : gctx_hi;
  const __half* Alo = (mode == 0) ? gx_lo : gctx_lo;
  const __half* Bhi = (mode == 0) ? gwin_hi : gwout_hi;

  float acc[4][8][4];
#pragma unroll
  for (int i = 0; i < 4; i++)
#pragma unroll
    for (int j = 0; j < 8; j++)
#pragma unroll
      for (int c = 0; c < 4; c++) acc[i][j][c] = 0.f;

  const int g = lane >> 3;
  const int rr = lane & 7;

  gemm_load_chunk(smem_base, 0, tid, Ahi, Alo, Bhi, m0, n0);
  CP_COMMIT();

  for (int c = 0; c < NCHUNK; c++) {
    const int buf = c & 1;
    if (c < NCHUNK - 1) {
      gemm_load_chunk(smem_base + (1 - buf) * GSTAGE, c + 1, tid, Ahi, Alo,
                      Bhi, m0, n0);
      CP_COMMIT();
      CP_WAIT(1);
    } else {
      CP_WAIT(0);
    }
    __syncthreads();

    const uint32_t sb = smem_base + buf * GSTAGE;
#pragma unroll
    for (int ks = 0; ks < 4; ks++) {
      uint32_t aH[4][4], aL[4][4], bH[4][4];
#pragma unroll
      for (int i = 0; i < 4; i++) {
        int row = wm + i * 16 + (g & 1) * 8 + rr;
        uint32_t off = SW128(row * 128 + ks * 32 + (g >> 1) * 16);
        ldmx4(aH[i], sb + GOFF_AHI + off);
        ldmx4(aL[i], sb + GOFF_ALO + off);
      }
#pragma unroll
      for (int jj = 0; jj < 4; jj++) {
        int row = wn + jj * 16 + (g >> 1) * 8 + rr;
        uint32_t off = SW128(row * 128 + ks * 32 + (g & 1) * 16);
        ldmx4(bH[jj], sb + GOFF_BHI + off);
      }
#pragma unroll
      for (int i = 0; i < 4; i++)
#pragma unroll
        for (int j = 0; j < 8; j++) {
          const uint32_t* bh = &bH[j >> 1][(j & 1) * 2];
          mma16816h(acc[i][j], aH[i], bh);
          mma16816h(acc[i][j], aL[i], bh);
        }
    }
    __syncthreads();
  }

  // Epilogue
#pragma unroll
  for (int i = 0; i < 4; i++) {
#pragma unroll
    for (int j = 0; j < 8; j++) {
      const int mr = m0 + wm + i * 16 + (lane >> 2);
      const int f = n0 + wn + j * 8 + (lane & 3) * 2;
      const float b0 = bias[f], b1 = bias[f + 1];
      float p00 = acc[i][j][0] + b0, p01 = acc[i][j][1] + b1;
      float p10 = acc[i][j][2] + b0, p11 = acc[i][j][3] + b1;
      if (mode == 0) {
        const int which = f >> 10;
        const int h = (f & 1023) >> 6;
        const int d0 = f & 63;
        const int t0 = mr >> 1, bb0 = mr & 1;
        const int t1 = (mr + 8) >> 1, bb1 = (mr + 8) & 1;
        size_t i0 = ((size_t)(bb0 * Hn + h) * Tn + t0) * Dn + d0;
        size_t i1 = ((size_t)(bb1 * Hn + h) * Tn + t1) * Dn + d0;
        if (which == 0) {        // q: fp16 hi/lo, pre-scaled by 1/8
          uint32_t h0, l0, h1, l1;
          split2h(p00 * 0.125f, p01 * 0.125f, h0, l0);
          split2h(p10 * 0.125f, p11 * 0.125f, h1, l1);
          *(uint32_t*)(gq_hi + i0) = h0; *(uint32_t*)(gq_lo + i0) = l0;
          *(uint32_t*)(gq_hi + i1) = h1; *(uint32_t*)(gq_lo + i1) = l1;
        } else if (which == 1) { // k: fp16 hi only
          *(uint32_t*)(gk_hi + i0) = cvt2h(p00, p01);
          *(uint32_t*)(gk_hi + i1) = cvt2h(p10, p11);
        } else {                 // v: fp16 hi/lo
          uint32_t h0, l0, h1, l1;
          split2h(p00, p01, h0, l0);
          split2h(p10, p11, h1, l1);
          *(uint32_t*)(gv_hi + i0) = h0; *(uint32_t*)(gv_lo + i0) = l0;
          *(uint32_t*)(gv_hi + i1) = h1; *(uint32_t*)(gv_lo + i1) = l1;
        }
      } else {
        *(float2*)(out + (size_t)mr * En + f) = make_float2(p00, p01);
        *(float2*)(out + (size_t)(mr + 8) * En + f) = make_float2(p10, p11);
      }
    }
  }
}

// ---------------------------------------------------------------------------
// fp16 HMMA flash attention: per CTA 128 queries x 1 head; 8 warps x 16 rows.
// 2-pass QK (qH*kH + qL*kH; k hi-only) and 2-pass PV (pH*vH + pH*vL).
// K/V 64-key chunks, double-buffered cp.async SW128 smem (24KB/stage).
// Q hi/lo tiles are 16KB each (128 rows x 128B).
// ---------------------------------------------------------------------------
#define A_OFF_KHI 0
#define A_OFF_VHI 8192
#define A_OFF_VLO 16384
#define A_STAGE 24576
#define A_OFF_QHI (2 * A_STAGE)            // 49152
#define A_OFF_QLO (2 * A_STAGE + 16384)    // 65536
#define ATTN_SMEM (2 * A_STAGE + 32768)    // 81920

__device__ __forceinline__ void attn_load_chunk(uint32_t sb, int stg, int j0,
                                                int tid,
                                                const __half* kh,
                                                const __half* vh,
                                                const __half* vl) {
  const uint32_t base = sb + stg * A_STAGE;
#pragma unroll
  for (int it = 0; it < 2; it++) {
    int vec = tid + it * 256;       // 0..511
    int r = vec >> 3, seg = vec & 7;
    uint32_t sw = SW128(r * 128 + seg * 16);
    size_t gi = ((size_t)(j0 + r)) * Dn + seg * 8;
    CP_ASYNC16(base + A_OFF_KHI + sw, kh + gi);
    CP_ASYNC16(base + A_OFF_VHI + sw, vh + gi);
    CP_ASYNC16(base + A_OFF_VLO + sw, vl + gi);
  }
}

__global__ __launch_bounds__(256, 1) void attn_hmma() {
  extern __shared__ __align__(1024) char smc[];
  const uint32_t sb = smem_u32(smc);
  const int tid = threadIdx.x;
  const int wid = tid >> 5;
  const int lane = tid & 31;
  const int g = lane >> 3;
  const int rr = lane & 7;
  const int bh = blockIdx.y;
  const int q0 = blockIdx.x * 128;

  const __half* qh = gq_hi + (size_t)bh * Tn * Dn;
  const __half* ql = gq_lo + (size_t)bh * Tn * Dn;
  const __half* kh = gk_hi + (size_t)bh * Tn * Dn;
  const __half* vh = gv_hi + (size_t)bh * Tn * Dn;
  const __half* vl = gv_lo + (size_t)bh * Tn * Dn;

  // Preamble: Q tile (hi/lo) + chunk 0, one commit group.
#pragma unroll
  for (int it = 0; it < 4; it++) {
    int vec = tid + it * 256;       // 0..1023
    int r = vec >> 3, seg = vec & 7;
    uint32_t sw = SW128(r * 128 + seg * 16);
    size_t gi = ((size_t)(q0 + r)) * Dn + seg * 8;
    CP_ASYNC16(sb + A_OFF_QHI + sw, qh + gi);
    CP_ASYNC16(sb + A_OFF_QLO + sw, ql + gi);
  }
  attn_load_chunk(sb, 0, 0, tid, kh, vh, vl);
  CP_COMMIT();
  CP_WAIT(0);
  __syncthreads();

  // Q fragments held in registers for the whole key loop
  uint32_t qH[4][4], qL[4][4];
#pragma unroll
  for (int ks = 0; ks < 4; ks++) {
    int row = wid * 16 + (g & 1) * 8 + rr;
    uint32_t off = SW128(row * 128 + ks * 32 + (g >> 1) * 16);
    ldmx4(qH[ks], sb + A_OFF_QHI + off);
    ldmx4(qL[ks], sb + A_OFF_QLO + off);
  }

  float o[8][4];
#pragma unroll
  for (int dt = 0; dt < 8; dt++)
#pragma unroll
    for (int c = 0; c < 4; c++) o[dt][c] = 0.f;
  float m_i[2] = {-1e30f, -1e30f};
  float l_i[2] = {0.f, 0.f};

  for (int c = 0; c < 32; c++) {
    const int buf = c & 1;
    if (c < 31) {
      attn_load_chunk(sb, 1 - buf, (c + 1) * 64, tid, kh, vh, vl);
      CP_COMMIT();
      CP_WAIT(1);
    } else {
      CP_WAIT(0);
    }
    __syncthreads();

    const uint32_t skh = sb + buf * A_STAGE + A_OFF_KHI;
    const uint32_t svh = sb + buf * A_STAGE + A_OFF_VHI;
    const uint32_t svl = sb + buf * A_STAGE + A_OFF_VLO;

    // ---- S = Q K^T (scaled: Q carries the 1/8); k hi-only, q corrected ----
    float s[8][4];
#pragma unroll
    for (int j = 0; j < 8; j++)
#pragma unroll
      for (int cc = 0; cc < 4; cc++) s[j][cc] = 0.f;

#pragma unroll
    for (int ks = 0; ks < 4; ks++) {
#pragma unroll
      for (int ng = 0; ng < 4; ng++) {
        uint32_t bkh[4];
        int row = ng * 16 + (g >> 1) * 8 + rr;
        uint32_t off = SW128(row * 128 + ks * 32 + (g & 1) * 16);
        ldmx4(bkh, skh + off);
#pragma unroll
        for (int hf = 0; hf < 2; hf++) {
          const int j = ng * 2 + hf;
          mma16816h(s[j], qH[ks], &bkh[hf * 2]);
          mma16816h(s[j], qL[ks], &bkh[hf * 2]);
        }
      }
    }

    // ---- online softmax (rows: l/4 and l/4+8) ----
#pragma unroll
    for (int r = 0; r < 2; r++) {
      float mx = -1e30f;
#pragma unroll
      for (int j = 0; j < 8; j++)
        mx = fmaxf(mx, fmaxf(s[j][2 * r], s[j][2 * r + 1]));
      mx = fmaxf(mx, __shfl_xor_sync(0xffffffffu, mx, 1));
      mx = fmaxf(mx, __shfl_xor_sync(0xffffffffu, mx, 2));
      float mnew = fmaxf(m_i[r], mx);
      float corr = __expf(m_i[r] - mnew);
      m_i[r] = mnew;
      float rs = 0.f;
#pragma unroll
      for (int j = 0; j < 8; j++) {
        float p0 = __expf(s[j][2 * r] - mnew);
        float p1 = __expf(s[j][2 * r + 1] - mnew);
        s[j][2 * r] = p0;
        s[j][2 * r + 1] = p1;
        rs += p0 + p1;
      }
      rs += __shfl_xor_sync(0xffffffffu, rs, 1);
      rs += __shfl_xor_sync(0xffffffffu, rs, 2);
      l_i[r] = l_i[r] * corr + rs;
#pragma unroll
      for (int dt = 0; dt < 8; dt++) {
        o[dt][2 * r] *= corr;
        o[dt][2 * r + 1] *= corr;
      }
    }

    // ---- O += P V (P single fp16; v hi+lo corrected) ----
#pragma unroll
    for (int kk = 0; kk < 4; kk++) {
      uint32_t pH[4];
      pH[0] = cvt2h(s[2 * kk][0], s[2 * kk][1]);
      pH[1] = cvt2h(s[2 * kk][2], s[2 * kk][3]);
      pH[2] = cvt2h(s[2 * kk + 1][0], s[2 * kk + 1][1]);
      pH[3] = cvt2h(s[2 * kk + 1][2], s[2 * kk + 1][3]);
#pragma unroll
      for (int dg = 0; dg < 4; dg++) {
        uint32_t bvh[4], bvl[4];
        int keyrow = kk * 16 + (g & 1) * 8 + rr;
        uint32_t off = SW128(keyrow * 128 + dg * 32 + (g >> 1) * 16);
        ldmx4t(bvh, svh + off);
        ldmx4t(bvl, svl + off);
#pragma unroll
        for (int hf = 0; hf < 2; hf++) {
          const int dt = dg * 2 + hf;
          mma16816h(o[dt], pH, &bvh[hf * 2]);
          mma16816h(o[dt], pH, &bvl[hf * 2]);
        }
      }
    }
    __syncthreads();
  }

  // Epilogue: normalize, split to fp16 hi/lo, write scrambled ctx layout:
  //   ctx[b][h*128 + t/16][(t&15)*64 + d]
  const int b = bh >> 4;
  const int h = bh & 15;
#pragma unroll
  for (int r = 0; r < 2; r++) {
    const float inv = 1.0f / l_i[r];
    const int t = q0 + wid * 16 + (lane >> 2) + r * 8;
    const int row = h * 128 + (t >> 4);
    const size_t base = ((size_t)(b * Tn + row)) * En + ((t & 15) << 6);
#pragma unroll
    for (int dt = 0; dt < 8; dt++) {
      const int d = dt * 8 + (lane & 3) * 2;
      uint32_t hw, lw;
      split2h(o[dt][2 * r] * inv, o[dt][2 * r + 1] * inv, hw, lw);
      *(uint32_t*)(gctx_hi + base + d) = hw;
      *(uint32_t*)(gctx_lo + base + d) = lw;
    }
  }
}

// ---------------------------------------------------------------------------
extern "C" void kernel_launch(void* const* d_in, const int* in_sizes, int n_in,
                              void* d_out, int out_size) {
  const float* x     = (const float*)d_in[0];  // (T, B, E)
  const float* w_in  = (const float*)d_in[1];  // (E, 3E)
  const float* b_in  = (const float*)d_in[2];  // (3E)
  const float* w_out = (const float*)d_in[3];  // (E, E)
  const float* b_out = (const float*)d_in[4];  // (E)
  float* out = (float*)d_out;                  // (B, T, E)

  cudaFuncSetAttribute(hmma_gemm, cudaFuncAttributeMaxDynamicSharedMemorySize,
                       GEMM_SMEM);
  cudaFuncSetAttribute(attn_hmma, cudaFuncAttributeMaxDynamicSharedMemorySize,
                       ATTN_SMEM);

  // fp16 conversions (x split hi/lo; weights hi-only, transposed)
  cvt_x<<<(Mrows * Kdim / 4 + 255) / 256, 256>>>(x);
  cvt_transpose<<<dim3(Pn / 32, Kdim / 32), dim3(32, 8)>>>(w_in, 0);
  cvt_transpose<<<dim3(En / 32, Kdim / 32), dim3(32, 8)>>>(w_out, 1);

  // 1) QKV projection (fp16 2-pass HMMA) -> q/k/v fp16 (q pre-scaled 1/8)
  hmma_gemm<<<dim3(Pn / 128, Mrows / 256), 256, GEMM_SMEM>>>(b_in, nullptr, 0);
  // 2) Attention (fp16 HMMA flash, 2-pass QK/PV) -> ctx fp16 splits
  attn_hmma<<<dim3(Tn / 128, BHn), 256, ATTN_SMEM>>>();
  // 3) Output projection (fp16 2-pass HMMA): M=4096, N=1024, K=1024
  hmma_gemm<<<dim3(En / 128, Mrows / 256), 256, GEMM_SMEM>>>(b_out, out, 1);
}

// round 11
// speedup vs baseline: 3.2470x; 1.4816x over previous
#include <cuda_runtime.h>
#include <cuda_fp16.h>
#include <math.h>
#include <cstdint>

// Problem dims (fixed by the reference)
#define Tn 2048
#define Bn 2
#define En 1024
#define Hn 16
#define Dn 64
#define BHn 32          // B*H
#define Pn 3072         // 3*E
#define Kdim 1024       // K of both GEMMs
#define Mrows 4096      // T*B

// ---------------------------------------------------------------------------
// Scratch: __device__ globals (allocation-free, graph-capturable)
// All operands plain fp16 (error budget validated rounds 9-10).
// ---------------------------------------------------------------------------
__device__ __half gx[(size_t)Mrows * Kdim];
__device__ __half gwin[(size_t)Pn * Kdim];   // in_proj_w^T [N][K]
__device__ __half gwout[(size_t)En * Kdim];  // out_w^T     [N][K]
__device__ __half gctx[(size_t)Mrows * Kdim];
// attention operands, layout [(b*H+h)][t][d]; q pre-scaled by 0.125
__device__ __half gq[(size_t)BHn * Tn * Dn];
__device__ __half gk[(size_t)BHn * Tn * Dn];
__device__ __half gv[(size_t)BHn * Tn * Dn];

// ---------------------------------------------------------------------------
// PTX helpers (sm_103-safe: mma.sync + ldmatrix + cp.async only)
// ---------------------------------------------------------------------------
__device__ __forceinline__ uint32_t smem_u32(const void* p) {
  uint32_t a;
  asm("{ .reg .u64 t; cvta.to.shared.u64 t, %1; cvt.u32.u64 %0, t; }"
      : "=r"(a) : "l"(p));
  return a;
}

#define SW128(off) ((uint32_t)(off) ^ ((((uint32_t)(off)) >> 3) & 0x70))

#define CP_ASYNC16(dst, src)                                       \
  asm volatile("cp.async.cg.shared.global [%0], [%1], 16;"         \
               :: "r"(dst), "l"(src) : "memory")
#define CP_COMMIT() asm volatile("cp.async.commit_group;" ::: "memory")
#define CP_WAIT(n) asm volatile("cp.async.wait_group %0;" :: "n"(n) : "memory")

__device__ __forceinline__ void ldmx4(uint32_t* r, uint32_t addr) {
  asm volatile(
      "ldmatrix.sync.aligned.m8n8.x4.shared.b16 {%0,%1,%2,%3}, [%4];"
      : "=r"(r[0]), "=r"(r[1]), "=r"(r[2]), "=r"(r[3]) : "r"(addr));
}
__device__ __forceinline__ void ldmx4t(uint32_t* r, uint32_t addr) {
  asm volatile(
      "ldmatrix.sync.aligned.m8n8.x4.trans.shared.b16 {%0,%1,%2,%3}, [%4];"
      : "=r"(r[0]), "=r"(r[1]), "=r"(r[2]), "=r"(r[3]) : "r"(addr));
}

// fp16 MMA, fp32 accumulate
__device__ __forceinline__ void mma16816h(float* c, const uint32_t* a,
                                          const uint32_t* b) {
  asm volatile(
      "mma.sync.aligned.m16n8k16.row.col.f32.f16.f16.f32 "
      "{%0,%1,%2,%3}, {%4,%5,%6,%7}, {%8,%9}, {%0,%1,%2,%3};"
      : "+f"(c[0]), "+f"(c[1]), "+f"(c[2]), "+f"(c[3])
      : "r"(a[0]), "r"(a[1]), "r"(a[2]), "r"(a[3]), "r"(b[0]), "r"(b[1]));
}

__device__ __forceinline__ uint32_t cvt2h(float p0, float p1) {
  __half2 hh = __float22half2_rn(make_float2(p0, p1));
  return *(uint32_t*)&hh;
}

// ---------------------------------------------------------------------------
// Conversion kernels: fp32 -> fp16
// ---------------------------------------------------------------------------
__global__ __launch_bounds__(256) void cvt_x(const float* __restrict__ xin) {
  size_t i = ((size_t)blockIdx.x * blockDim.x + threadIdx.x) * 4;
  if (i < (size_t)Mrows * Kdim) {
    float4 v = *(const float4*)(xin + i);
    uint2 hw = make_uint2(cvt2h(v.x, v.y), cvt2h(v.z, v.w));
    *(uint2*)(gx + i) = hw;
  }
}

// Transpose W[K][N] -> Wt [N][K] (fp16). which: 0=in_proj, 1=out
__global__ __launch_bounds__(256) void cvt_transpose(const float* __restrict__ W,
                                                     int which) {
  __half* dst = (which == 0) ? gwin : gwout;
  const int N = (which == 0) ? Pn : En;
  __shared__ float t[32][33];
  const int n0 = blockIdx.x * 32, k0 = blockIdx.y * 32;
  const int tx = threadIdx.x, ty = threadIdx.y;  // 32 x 8
#pragma unroll
  for (int i = ty; i < 32; i += 8)
    t[i][tx] = W[(size_t)(k0 + i) * N + n0 + tx];
  __syncthreads();
#pragma unroll
  for (int j = ty; j < 32; j += 8)
    dst[(size_t)(n0 + j) * Kdim + k0 + tx] = __float2half(t[tx][j]);
}

// ---------------------------------------------------------------------------
// fp16 HMMA GEMM (single-pass): per CTA D[256 x 128] = A[M,K] * B^T[N,K] + bias
// BK=64, SW128, 48KB/stage double-buffered (96KB smem). 8 warps, 64x64 each.
//   mode 0: A = x, B = in_proj^T; epilogue -> q/k/v fp16 (q scaled 1/8)
//   mode 1: A = ctx, B = out_w^T; epilogue -> fp32 d_out
// ---------------------------------------------------------------------------
#define GOFF_A 0
#define GOFF_B 32768
#define GSTAGE 49152
#define GEMM_SMEM (2 * GSTAGE)  // 96 KB
#define NCHUNK (Kdim / 64)      // 16

__device__ __forceinline__ void gemm_load_chunk(
    uint32_t sb, int kc, int tid,
    const __half* __restrict__ A, const __half* __restrict__ B,
    int m0, int n0) {
  const int k0 = kc * 64;
#pragma unroll
  for (int it = 0; it < 8; it++) {      // A: 256 rows x 8 segs of 16B
    const int v = tid + it * 256;
    const int row = v >> 3, seg = v & 7;
    const uint32_t sw = SW128(row * 128 + seg * 16);
    const size_t gi = (size_t)(m0 + row) * Kdim + k0 + seg * 8;
    CP_ASYNC16(sb + GOFF_A + sw, A + gi);
  }
#pragma unroll
  for (int it = 0; it < 4; it++) {      // B: 128 rows x 8 segs of 16B
    const int v = tid + it * 256;
    const int row = v >> 3, seg = v & 7;
    const uint32_t sw = SW128(row * 128 + seg * 16);
    const size_t gi = (size_t)(n0 + row) * Kdim + k0 + seg * 8;
    CP_ASYNC16(sb + GOFF_B + sw, B + gi);
  }
}

__global__ __launch_bounds__(256) void hmma_gemm(
    const float* __restrict__ bias, float* __restrict__ out, int mode) {
  extern __shared__ __align__(1024) char smc[];
  const uint32_t smem_base = smem_u32(smc);
  const int tid = threadIdx.x;
  const int wid = tid >> 5;
  const int lane = tid & 31;
  const int m0 = blockIdx.y * 256;
  const int n0 = blockIdx.x * 128;
  const int wm = (wid & 3) * 64;   // 4 warps along M
  const int wn = (wid >> 2) * 64;  // 2 warps along N

  const __half* A = (mode == 0) ? gx : gctx;
  const __half* B = (mode == 0) ? gwin : gwout;

  float acc[4][8][4];
#pragma unroll
  for (int i = 0; i < 4; i++)
#pragma unroll
    for (int j = 0; j < 8; j++)
#pragma unroll
      for (int c = 0; c < 4; c++) acc[i][j][c] = 0.f;

  const int g = lane >> 3;
  const int rr = lane & 7;

  gemm_load_chunk(smem_base, 0, tid, A, B, m0, n0);
  CP_COMMIT();

  for (int c = 0; c < NCHUNK; c++) {
    const int buf = c & 1;
    if (c < NCHUNK - 1) {
      gemm_load_chunk(smem_base + (1 - buf) * GSTAGE, c + 1, tid, A, B, m0, n0);
      CP_COMMIT();
      CP_WAIT(1);
    } else {
      CP_WAIT(0);
    }
    __syncthreads();

    const uint32_t sb = smem_base + buf * GSTAGE;
#pragma unroll
    for (int ks = 0; ks < 4; ks++) {
      uint32_t aF[4][4], bF[4][4];
#pragma unroll
      for (int i = 0; i < 4; i++) {
        int row = wm + i * 16 + (g & 1) * 8 + rr;
        uint32_t off = SW128(row * 128 + ks * 32 + (g >> 1) * 16);
        ldmx4(aF[i], sb + GOFF_A + off);
      }
#pragma unroll
      for (int jj = 0; jj < 4; jj++) {
        int row = wn + jj * 16 + (g >> 1) * 8 + rr;
        uint32_t off = SW128(row * 128 + ks * 32 + (g & 1) * 16);
        ldmx4(bF[jj], sb + GOFF_B + off);
      }
#pragma unroll
      for (int i = 0; i < 4; i++)
#pragma unroll
        for (int j = 0; j < 8; j++)
          mma16816h(acc[i][j], aF[i], &bF[j >> 1][(j & 1) * 2]);
    }
    __syncthreads();
  }

  // Epilogue
#pragma unroll
  for (int i = 0; i < 4; i++) {
#pragma unroll
    for (int j = 0; j < 8; j++) {
      const int mr = m0 + wm + i * 16 + (lane >> 2);
      const int f = n0 + wn + j * 8 + (lane & 3) * 2;
      const float b0 = bias[f], b1 = bias[f + 1];
      float p00 = acc[i][j][0] + b0, p01 = acc[i][j][1] + b1;
      float p10 = acc[i][j][2] + b0, p11 = acc[i][j][3] + b1;
      if (mode == 0) {
        const int which = f >> 10;
        const int h = (f & 1023) >> 6;
        const int d0 = f & 63;
        const int t0 = mr >> 1, bb0 = mr & 1;
        const int t1 = (mr + 8) >> 1, bb1 = (mr + 8) & 1;
        size_t i0 = ((size_t)(bb0 * Hn + h) * Tn + t0) * Dn + d0;
        size_t i1 = ((size_t)(bb1 * Hn + h) * Tn + t1) * Dn + d0;
        __half* dst = (which == 0) ? gq : (which == 1) ? gk : gv;
        const float sc = (which == 0) ? 0.125f : 1.f;
        *(uint32_t*)(dst + i0) = cvt2h(p00 * sc, p01 * sc);
        *(uint32_t*)(dst + i1) = cvt2h(p10 * sc, p11 * sc);
      } else {
        *(float2*)(out + (size_t)mr * En + f) = make_float2(p00, p01);
        *(float2*)(out + (size_t)(mr + 8) * En + f) = make_float2(p10, p11);
      }
    }
  }
}

// ---------------------------------------------------------------------------
// fp16 HMMA flash attention (single-pass): per CTA 128 queries x 1 head;
// 8 warps x 16 rows. K/V 64-key chunks, double-buffered SW128 smem (16KB/stage).
// Q tile 16KB.
// ---------------------------------------------------------------------------
#define A_OFF_K 0
#define A_OFF_V 8192
#define A_STAGE 16384
#define A_OFF_Q (2 * A_STAGE)          // 32768
#define ATTN_SMEM (2 * A_STAGE + 16384)  // 49152

__device__ __forceinline__ void attn_load_chunk(uint32_t sb, int stg, int j0,
                                                int tid, const __half* kp,
                                                const __half* vp) {
  const uint32_t base = sb + stg * A_STAGE;
#pragma unroll
  for (int it = 0; it < 2; it++) {
    int vec = tid + it * 256;       // 0..511
    int r = vec >> 3, seg = vec & 7;
    uint32_t sw = SW128(r * 128 + seg * 16);
    size_t gi = ((size_t)(j0 + r)) * Dn + seg * 8;
    CP_ASYNC16(base + A_OFF_K + sw, kp + gi);
    CP_ASYNC16(base + A_OFF_V + sw, vp + gi);
  }
}

__global__ __launch_bounds__(256, 1) void attn_hmma() {
  extern __shared__ __align__(1024) char smc[];
  const uint32_t sb = smem_u32(smc);
  const int tid = threadIdx.x;
  const int wid = tid >> 5;
  const int lane = tid & 31;
  const int g = lane >> 3;
  const int rr = lane & 7;
  const int bh = blockIdx.y;
  const int q0 = blockIdx.x * 128;

  const __half* qp = gq + (size_t)bh * Tn * Dn;
  const __half* kp = gk + (size_t)bh * Tn * Dn;
  const __half* vp = gv + (size_t)bh * Tn * Dn;

  // Preamble: Q tile + chunk 0, one commit group.
#pragma unroll
  for (int it = 0; it < 4; it++) {
    int vec = tid + it * 256;       // 0..1023
    int r = vec >> 3, seg = vec & 7;
    uint32_t sw = SW128(r * 128 + seg * 16);
    CP_ASYNC16(sb + A_OFF_Q + sw, qp + ((size_t)(q0 + r)) * Dn + seg * 8);
  }
  attn_load_chunk(sb, 0, 0, tid, kp, vp);
  CP_COMMIT();
  CP_WAIT(0);
  __syncthreads();

  // Q fragments held in registers for the whole key loop
  uint32_t qF[4][4];
#pragma unroll
  for (int ks = 0; ks < 4; ks++) {
    int row = wid * 16 + (g & 1) * 8 + rr;
    uint32_t off = SW128(row * 128 + ks * 32 + (g >> 1) * 16);
    ldmx4(qF[ks], sb + A_OFF_Q + off);
  }

  float o[8][4];
#pragma unroll
  for (int dt = 0; dt < 8; dt++)
#pragma unroll
    for (int c = 0; c < 4; c++) o[dt][c] = 0.f;
  float m_i[2] = {-1e30f, -1e30f};
  float l_i[2] = {0.f, 0.f};

  for (int c = 0; c < 32; c++) {
    const int buf = c & 1;
    if (c < 31) {
      attn_load_chunk(sb, 1 - buf, (c + 1) * 64, tid, kp, vp);
      CP_COMMIT();
      CP_WAIT(1);
    } else {
      CP_WAIT(0);
    }
    __syncthreads();

    const uint32_t sk = sb + buf * A_STAGE + A_OFF_K;
    const uint32_t sv = sb + buf * A_STAGE + A_OFF_V;

    // ---- S = Q K^T (Q carries the 1/8) ----
    float s[8][4];
#pragma unroll
    for (int j = 0; j < 8; j++)
#pragma unroll
      for (int cc = 0; cc < 4; cc++) s[j][cc] = 0.f;

#pragma unroll
    for (int ks = 0; ks < 4; ks++) {
#pragma unroll
      for (int ng = 0; ng < 4; ng++) {
        uint32_t bk[4];
        int row = ng * 16 + (g >> 1) * 8 + rr;
        uint32_t off = SW128(row * 128 + ks * 32 + (g & 1) * 16);
        ldmx4(bk, sk + off);
#pragma unroll
        for (int hf = 0; hf < 2; hf++)
          mma16816h(s[ng * 2 + hf], qF[ks], &bk[hf * 2]);
      }
    }

    // ---- online softmax (rows: l/4 and l/4+8) ----
#pragma unroll
    for (int r = 0; r < 2; r++) {
      float mx = -1e30f;
#pragma unroll
      for (int j = 0; j < 8; j++)
        mx = fmaxf(mx, fmaxf(s[j][2 * r], s[j][2 * r + 1]));
      mx = fmaxf(mx, __shfl_xor_sync(0xffffffffu, mx, 1));
      mx = fmaxf(mx, __shfl_xor_sync(0xffffffffu, mx, 2));
      float mnew = fmaxf(m_i[r], mx);
      float corr = __expf(m_i[r] - mnew);
      m_i[r] = mnew;
      float rs = 0.f;
#pragma unroll
      for (int j = 0; j < 8; j++) {
        float p0 = __expf(s[j][2 * r] - mnew);
        float p1 = __expf(s[j][2 * r + 1] - mnew);
        s[j][2 * r] = p0;
        s[j][2 * r + 1] = p1;
        rs += p0 + p1;
      }
      rs += __shfl_xor_sync(0xffffffffu, rs, 1);
      rs += __shfl_xor_sync(0xffffffffu, rs, 2);
      l_i[r] = l_i[r] * corr + rs;
#pragma unroll
      for (int dt = 0; dt < 8; dt++) {
        o[dt][2 * r] *= corr;
        o[dt][2 * r + 1] *= corr;
      }
    }

    // ---- O += P V ----
#pragma unroll
    for (int kk = 0; kk < 4; kk++) {
      uint32_t pF[4];
      pF[0] = cvt2h(s[2 * kk][0], s[2 * kk][1]);
      pF[1] = cvt2h(s[2 * kk][2], s[2 * kk][3]);
      pF[2] = cvt2h(s[2 * kk + 1][0], s[2 * kk + 1][1]);
      pF[3] = cvt2h(s[2 * kk + 1][2], s[2 * kk + 1][3]);
#pragma unroll
      for (int dg = 0; dg < 4; dg++) {
        uint32_t bv[4];
        int keyrow = kk * 16 + (g & 1) * 8 + rr;
        uint32_t off = SW128(keyrow * 128 + dg * 32 + (g >> 1) * 16);
        ldmx4t(bv, sv + off);
#pragma unroll
        for (int hf = 0; hf < 2; hf++)
          mma16816h(o[dg * 2 + hf], pF, &bv[hf * 2]);
      }
    }
    __syncthreads();
  }

  // Epilogue: normalize, write fp16 ctx in the scrambled layout:
  //   ctx[b][h*128 + t/16][(t&15)*64 + d]
  const int b = bh >> 4;
  const int h = bh & 15;
#pragma unroll
  for (int r = 0; r < 2; r++) {
    const float inv = 1.0f / l_i[r];
    const int t = q0 + wid * 16 + (lane >> 2) + r * 8;
    const int row = h * 128 + (t >> 4);
    const size_t base = ((size_t)(b * Tn + row)) * En + ((t & 15) << 6);
#pragma unroll
    for (int dt = 0; dt < 8; dt++) {
      const int d = dt * 8 + (lane & 3) * 2;
      *(uint32_t*)(gctx + base + d) =
          cvt2h(o[dt][2 * r] * inv, o[dt][2 * r + 1] * inv);
    }
  }
}

// ---------------------------------------------------------------------------
extern "C" void kernel_launch(void* const* d_in, const int* in_sizes, int n_in,
                              void* d_out, int out_size) {
  const float* x     = (const float*)d_in[0];  // (T, B, E)
  const float* w_in  = (const float*)d_in[1];  // (E, 3E)
  const float* b_in  = (const float*)d_in[2];  // (3E)
  const float* w_out = (const float*)d_in[3];  // (E, E)
  const float* b_out = (const float*)d_in[4];  // (E)
  float* out = (float*)d_out;                  // (B, T, E)

  cudaFuncSetAttribute(hmma_gemm, cudaFuncAttributeMaxDynamicSharedMemorySize,
                       GEMM_SMEM);
  cudaFuncSetAttribute(attn_hmma, cudaFuncAttributeMaxDynamicSharedMemorySize,
                       ATTN_SMEM);

  // fp16 conversions
  cvt_x<<<(Mrows * Kdim / 4 + 255) / 256, 256>>>(x);
  cvt_transpose<<<dim3(Pn / 32, Kdim / 32), dim3(32, 8)>>>(w_in, 0);
  cvt_transpose<<<dim3(En / 32, Kdim / 32), dim3(32, 8)>>>(w_out, 1);

  // 1) QKV projection (fp16 1-pass HMMA) -> q/k/v fp16 (q pre-scaled 1/8)
  hmma_gemm<<<dim3(Pn / 128, Mrows / 256), 256, GEMM_SMEM>>>(b_in, nullptr, 0);
  // 2) Attention (fp16 HMMA flash, 1-pass) -> ctx fp16
  attn_hmma<<<dim3(Tn / 128, BHn), 256, ATTN_SMEM>>>();
  // 3) Output projection (fp16 1-pass HMMA): M=4096, N=1024, K=1024
  hmma_gemm<<<dim3(En / 128, Mrows / 256), 256, GEMM_SMEM>>>(b_out, out, 1);
}

// round 12
// speedup vs baseline: 3.5319x; 1.0877x over previous
#include <cuda_runtime.h>
#include <cuda_fp16.h>
#include <math.h>
#include <cstdint>

// Problem dims (fixed by the reference)
#define Tn 2048
#define Bn 2
#define En 1024
#define Hn 16
#define Dn 64
#define BHn 32          // B*H
#define Pn 3072         // 3*E
#define Kdim 1024       // K of both GEMMs
#define Mrows 4096      // T*B

// ---------------------------------------------------------------------------
// Scratch: __device__ globals (allocation-free, graph-capturable)
// ---------------------------------------------------------------------------
__device__ __half gx[(size_t)Mrows * Kdim];
__device__ __half gwin[(size_t)Pn * Kdim];   // in_proj_w^T [N][K]
__device__ __half gwout[(size_t)En * Kdim];  // out_w^T     [N][K]
__device__ __half gctx[(size_t)Mrows * Kdim];
// attention operands, layout [(b*H+h)][t][d]; q pre-scaled by 0.125
__device__ __half gq[(size_t)BHn * Tn * Dn];
__device__ __half gk[(size_t)BHn * Tn * Dn];
__device__ __half gv[(size_t)BHn * Tn * Dn];

// ---------------------------------------------------------------------------
// PTX helpers (sm_103-safe: mma.sync + ldmatrix + cp.async only)
// ---------------------------------------------------------------------------
__device__ __forceinline__ uint32_t smem_u32(const void* p) {
  uint32_t a;
  asm("{ .reg .u64 t; cvta.to.shared.u64 t, %1; cvt.u32.u64 %0, t; }"
      : "=r"(a) : "l"(p));
  return a;
}

#define SW128(off) ((uint32_t)(off) ^ ((((uint32_t)(off)) >> 3) & 0x70))

#define CP_ASYNC16(dst, src)                                       \
  asm volatile("cp.async.cg.shared.global [%0], [%1], 16;"         \
               :: "r"(dst), "l"(src) : "memory")
#define CP_COMMIT() asm volatile("cp.async.commit_group;" ::: "memory")
#define CP_WAIT(n) asm volatile("cp.async.wait_group %0;" :: "n"(n) : "memory")

__device__ __forceinline__ void ldmx4(uint32_t* r, uint32_t addr) {
  asm volatile(
      "ldmatrix.sync.aligned.m8n8.x4.shared.b16 {%0,%1,%2,%3}, [%4];"
      : "=r"(r[0]), "=r"(r[1]), "=r"(r[2]), "=r"(r[3]) : "r"(addr));
}
__device__ __forceinline__ void ldmx4t(uint32_t* r, uint32_t addr) {
  asm volatile(
      "ldmatrix.sync.aligned.m8n8.x4.trans.shared.b16 {%0,%1,%2,%3}, [%4];"
      : "=r"(r[0]), "=r"(r[1]), "=r"(r[2]), "=r"(r[3]) : "r"(addr));
}

// fp16 MMA, fp32 accumulate
__device__ __forceinline__ void mma16816h(float* c, const uint32_t* a,
                                          const uint32_t* b) {
  asm volatile(
      "mma.sync.aligned.m16n8k16.row.col.f32.f16.f16.f32 "
      "{%0,%1,%2,%3}, {%4,%5,%6,%7}, {%8,%9}, {%0,%1,%2,%3};"
      : "+f"(c[0]), "+f"(c[1]), "+f"(c[2]), "+f"(c[3])
      : "r"(a[0]), "r"(a[1]), "r"(a[2]), "r"(a[3]), "r"(b[0]), "r"(b[1]));
}

__device__ __forceinline__ uint32_t cvt2h(float p0, float p1) {
  __half2 hh = __float22half2_rn(make_float2(p0, p1));
  return *(uint32_t*)&hh;
}

// ---------------------------------------------------------------------------
// Conversion kernels: fp32 -> fp16
// ---------------------------------------------------------------------------
__global__ __launch_bounds__(256) void cvt_x(const float* __restrict__ xin) {
  size_t i = ((size_t)blockIdx.x * blockDim.x + threadIdx.x) * 4;
  if (i < (size_t)Mrows * Kdim) {
    float4 v = *(const float4*)(xin + i);
    uint2 hw = make_uint2(cvt2h(v.x, v.y), cvt2h(v.z, v.w));
    *(uint2*)(gx + i) = hw;
  }
}

// Transpose W[K][N] -> Wt [N][K] (fp16). which: 0=in_proj, 1=out
__global__ __launch_bounds__(256) void cvt_transpose(const float* __restrict__ W,
                                                     int which) {
  __half* dst = (which == 0) ? gwin : gwout;
  const int N = (which == 0) ? Pn : En;
  __shared__ float t[32][33];
  const int n0 = blockIdx.x * 32, k0 = blockIdx.y * 32;
  const int tx = threadIdx.x, ty = threadIdx.y;  // 32 x 8
#pragma unroll
  for (int i = ty; i < 32; i += 8)
    t[i][tx] = W[(size_t)(k0 + i) * N + n0 + tx];
  __syncthreads();
#pragma unroll
  for (int j = ty; j < 32; j += 8)
    dst[(size_t)(n0 + j) * Kdim + k0 + tx] = __float2half(t[tx][j]);
}

// ---------------------------------------------------------------------------
// fp16 HMMA GEMM (single-pass): per CTA D[256 x 128] = A[M,K] * B^T[N,K] + bias
// BK=128 (two BK=64 sub-chunks per stage), double-buffered: 8 syncs total.
// Stage = A(2x32KB) + B(2x16KB) = 96KB; 2 stages = 192KB smem.
//   mode 0: A = x, B = in_proj^T; epilogue -> q/k/v fp16 (q scaled 1/8)
//   mode 1: A = ctx, B = out_w^T; epilogue -> fp32 d_out
// ---------------------------------------------------------------------------
#define GOFF_A 0            // A sub0 at 0, A sub1 at 32768
#define GOFF_B 65536        // B sub0 at 65536, B sub1 at 81920
#define GSUB_A 32768
#define GSUB_B 16384
#define GSTAGE 98304
#define GEMM_SMEM (2 * GSTAGE)  // 192 KB
#define NCHUNK (Kdim / 128)     // 8

// Load one BK=64 sub-chunk into (sb + sub offsets).
__device__ __forceinline__ void gemm_load_sub(
    uint32_t sb, int sub, int k0, int tid,
    const __half* __restrict__ A, const __half* __restrict__ B,
    int m0, int n0) {
  const uint32_t abase = sb + GOFF_A + sub * GSUB_A;
  const uint32_t bbase = sb + GOFF_B + sub * GSUB_B;
#pragma unroll
  for (int it = 0; it < 8; it++) {      // A: 256 rows x 8 segs of 16B
    const int v = tid + it * 256;
    const int row = v >> 3, seg = v & 7;
    const uint32_t sw = SW128(row * 128 + seg * 16);
    CP_ASYNC16(abase + sw, A + (size_t)(m0 + row) * Kdim + k0 + seg * 8);
  }
#pragma unroll
  for (int it = 0; it < 4; it++) {      // B: 128 rows x 8 segs of 16B
    const int v = tid + it * 256;
    const int row = v >> 3, seg = v & 7;
    const uint32_t sw = SW128(row * 128 + seg * 16);
    CP_ASYNC16(bbase + sw, B + (size_t)(n0 + row) * Kdim + k0 + seg * 8);
  }
}

__global__ __launch_bounds__(256) void hmma_gemm(
    const float* __restrict__ bias, float* __restrict__ out, int mode) {
  extern __shared__ __align__(1024) char smc[];
  const uint32_t smem_base = smem_u32(smc);
  const int tid = threadIdx.x;
  const int wid = tid >> 5;
  const int lane = tid & 31;
  const int m0 = blockIdx.y * 256;
  const int n0 = blockIdx.x * 128;
  const int wm = (wid & 3) * 64;   // 4 warps along M
  const int wn = (wid >> 2) * 64;  // 2 warps along N

  const __half* A = (mode == 0) ? gx : gctx;
  const __half* B = (mode == 0) ? gwin : gwout;

  float acc[4][8][4];
#pragma unroll
  for (int i = 0; i < 4; i++)
#pragma unroll
    for (int j = 0; j < 8; j++)
#pragma unroll
      for (int c = 0; c < 4; c++) acc[i][j][c] = 0.f;

  const int g = lane >> 3;
  const int rr = lane & 7;

  gemm_load_sub(smem_base, 0, 0, tid, A, B, m0, n0);
  gemm_load_sub(smem_base, 1, 64, tid, A, B, m0, n0);
  CP_COMMIT();

  for (int c = 0; c < NCHUNK; c++) {
    const int buf = c & 1;
    if (c < NCHUNK - 1) {
      const uint32_t nb = smem_base + (1 - buf) * GSTAGE;
      gemm_load_sub(nb, 0, (c + 1) * 128, tid, A, B, m0, n0);
      gemm_load_sub(nb, 1, (c + 1) * 128 + 64, tid, A, B, m0, n0);
      CP_COMMIT();
      CP_WAIT(1);
    } else {
      CP_WAIT(0);
    }
    __syncthreads();

    const uint32_t sb = smem_base + buf * GSTAGE;
#pragma unroll
    for (int ks = 0; ks < 8; ks++) {
      const int sub = ks >> 2;
      const int kq = ks & 3;
      const uint32_t abase = sb + GOFF_A + sub * GSUB_A;
      const uint32_t bbase = sb + GOFF_B + sub * GSUB_B;
      uint32_t aF[4][4], bF[4][4];
#pragma unroll
      for (int i = 0; i < 4; i++) {
        int row = wm + i * 16 + (g & 1) * 8 + rr;
        ldmx4(aF[i], abase + SW128(row * 128 + kq * 32 + (g >> 1) * 16));
      }
#pragma unroll
      for (int jj = 0; jj < 4; jj++) {
        int row = wn + jj * 16 + (g >> 1) * 8 + rr;
        ldmx4(bF[jj], bbase + SW128(row * 128 + kq * 32 + (g & 1) * 16));
      }
#pragma unroll
      for (int i = 0; i < 4; i++)
#pragma unroll
        for (int j = 0; j < 8; j++)
          mma16816h(acc[i][j], aF[i], &bF[j >> 1][(j & 1) * 2]);
    }
    __syncthreads();
  }

  // Epilogue
#pragma unroll
  for (int i = 0; i < 4; i++) {
#pragma unroll
    for (int j = 0; j < 8; j++) {
      const int mr = m0 + wm + i * 16 + (lane >> 2);
      const int f = n0 + wn + j * 8 + (lane & 3) * 2;
      const float b0 = bias[f], b1 = bias[f + 1];
      float p00 = acc[i][j][0] + b0, p01 = acc[i][j][1] + b1;
      float p10 = acc[i][j][2] + b0, p11 = acc[i][j][3] + b1;
      if (mode == 0) {
        const int which = f >> 10;
        const int h = (f & 1023) >> 6;
        const int d0 = f & 63;
        const int t0 = mr >> 1, bb0 = mr & 1;
        const int t1 = (mr + 8) >> 1, bb1 = (mr + 8) & 1;
        size_t i0 = ((size_t)(bb0 * Hn + h) * Tn + t0) * Dn + d0;
        size_t i1 = ((size_t)(bb1 * Hn + h) * Tn + t1) * Dn + d0;
        __half* dst = (which == 0) ? gq : (which == 1) ? gk : gv;
        const float sc = (which == 0) ? 0.125f : 1.f;
        *(uint32_t*)(dst + i0) = cvt2h(p00 * sc, p01 * sc);
        *(uint32_t*)(dst + i1) = cvt2h(p10 * sc, p11 * sc);
      } else {
        *(float2*)(out + (size_t)mr * En + f) = make_float2(p00, p01);
        *(float2*)(out + (size_t)(mr + 8) * En + f) = make_float2(p10, p11);
      }
    }
  }
}

// ---------------------------------------------------------------------------
// fp16 HMMA flash attention (single-pass): per CTA 128 queries x 1 head;
// 8 warps x 16 rows. K/V 64-key chunks, double-buffered SW128 smem (16KB/stage).
// Q tile 16KB. 48KB total -> __launch_bounds__(256,2) = 2 CTAs/SM to hide the
// serial softmax phases with a co-resident CTA's MMA work.
// ---------------------------------------------------------------------------
#define A_OFF_K 0
#define A_OFF_V 8192
#define A_STAGE 16384
#define A_OFF_Q (2 * A_STAGE)          // 32768
#define ATTN_SMEM (2 * A_STAGE + 16384)  // 49152

__device__ __forceinline__ void attn_load_chunk(uint32_t sb, int stg, int j0,
                                                int tid, const __half* kp,
                                                const __half* vp) {
  const uint32_t base = sb + stg * A_STAGE;
#pragma unroll
  for (int it = 0; it < 2; it++) {
    int vec = tid + it * 256;       // 0..511
    int r = vec >> 3, seg = vec & 7;
    uint32_t sw = SW128(r * 128 + seg * 16);
    size_t gi = ((size_t)(j0 + r)) * Dn + seg * 8;
    CP_ASYNC16(base + A_OFF_K + sw, kp + gi);
    CP_ASYNC16(base + A_OFF_V + sw, vp + gi);
  }
}

__global__ __launch_bounds__(256, 2) void attn_hmma() {
  extern __shared__ __align__(1024) char smc[];
  const uint32_t sb = smem_u32(smc);
  const int tid = threadIdx.x;
  const int wid = tid >> 5;
  const int lane = tid & 31;
  const int g = lane >> 3;
  const int rr = lane & 7;
  const int bh = blockIdx.y;
  const int q0 = blockIdx.x * 128;

  const __half* qp = gq + (size_t)bh * Tn * Dn;
  const __half* kp = gk + (size_t)bh * Tn * Dn;
  const __half* vp = gv + (size_t)bh * Tn * Dn;

  // Preamble: Q tile + chunk 0, one commit group.
#pragma unroll
  for (int it = 0; it < 4; it++) {
    int vec = tid + it * 256;       // 0..1023
    int r = vec >> 3, seg = vec & 7;
    uint32_t sw = SW128(r * 128 + seg * 16);
    CP_ASYNC16(sb + A_OFF_Q + sw, qp + ((size_t)(q0 + r)) * Dn + seg * 8);
  }
  attn_load_chunk(sb, 0, 0, tid, kp, vp);
  CP_COMMIT();
  CP_WAIT(0);
  __syncthreads();

  // Q fragments held in registers for the whole key loop
  uint32_t qF[4][4];
#pragma unroll
  for (int ks = 0; ks < 4; ks++) {
    int row = wid * 16 + (g & 1) * 8 + rr;
    uint32_t off = SW128(row * 128 + ks * 32 + (g >> 1) * 16);
    ldmx4(qF[ks], sb + A_OFF_Q + off);
  }

  float o[8][4];
#pragma unroll
  for (int dt = 0; dt < 8; dt++)
#pragma unroll
    for (int c = 0; c < 4; c++) o[dt][c] = 0.f;
  float m_i[2] = {-1e30f, -1e30f};
  float l_i[2] = {0.f, 0.f};

  for (int c = 0; c < 32; c++) {
    const int buf = c & 1;
    if (c < 31) {
      attn_load_chunk(sb, 1 - buf, (c + 1) * 64, tid, kp, vp);
      CP_COMMIT();
      CP_WAIT(1);
    } else {
      CP_WAIT(0);
    }
    __syncthreads();

    const uint32_t sk = sb + buf * A_STAGE + A_OFF_K;
    const uint32_t sv = sb + buf * A_STAGE + A_OFF_V;

    // ---- S = Q K^T (Q carries the 1/8) ----
    float s[8][4];
#pragma unroll
    for (int j = 0; j < 8; j++)
#pragma unroll
      for (int cc = 0; cc < 4; cc++) s[j][cc] = 0.f;

#pragma unroll
    for (int ks = 0; ks < 4; ks++) {
#pragma unroll
      for (int ng = 0; ng < 4; ng++) {
        uint32_t bk[4];
        int row = ng * 16 + (g >> 1) * 8 + rr;
        uint32_t off = SW128(row * 128 + ks * 32 + (g & 1) * 16);
        ldmx4(bk, sk + off);
#pragma unroll
        for (int hf = 0; hf < 2; hf++)
          mma16816h(s[ng * 2 + hf], qF[ks], &bk[hf * 2]);
      }
    }

    // ---- online softmax (rows: l/4 and l/4+8) ----
#pragma unroll
    for (int r = 0; r < 2; r++) {
      float mx = -1e30f;
#pragma unroll
      for (int j = 0; j < 8; j++)
        mx = fmaxf(mx, fmaxf(s[j][2 * r], s[j][2 * r + 1]));
      mx = fmaxf(mx, __shfl_xor_sync(0xffffffffu, mx, 1));
      mx = fmaxf(mx, __shfl_xor_sync(0xffffffffu, mx, 2));
      float mnew = fmaxf(m_i[r], mx);
      float corr = __expf(m_i[r] - mnew);
      m_i[r] = mnew;
      float rs = 0.f;
#pragma unroll
      for (int j = 0; j < 8; j++) {
        float p0 = __expf(s[j][2 * r] - mnew);
        float p1 = __expf(s[j][2 * r + 1] - mnew);
        s[j][2 * r] = p0;
        s[j][2 * r + 1] = p1;
        rs += p0 + p1;
      }
      rs += __shfl_xor_sync(0xffffffffu, rs, 1);
      rs += __shfl_xor_sync(0xffffffffu, rs, 2);
      l_i[r] = l_i[r] * corr + rs;
#pragma unroll
      for (int dt = 0; dt < 8; dt++) {
        o[dt][2 * r] *= corr;
        o[dt][2 * r + 1] *= corr;
      }
    }

    // ---- O += P V ----
#pragma unroll
    for (int kk = 0; kk < 4; kk++) {
      uint32_t pF[4];
      pF[0] = cvt2h(s[2 * kk][0], s[2 * kk][1]);
      pF[1] = cvt2h(s[2 * kk][2], s[2 * kk][3]);
      pF[2] = cvt2h(s[2 * kk + 1][0], s[2 * kk + 1][1]);
      pF[3] = cvt2h(s[2 * kk + 1][2], s[2 * kk + 1][3]);
#pragma unroll
      for (int dg = 0; dg < 4; dg++) {
        uint32_t bv[4];
        int keyrow = kk * 16 + (g & 1) * 8 + rr;
        uint32_t off = SW128(keyrow * 128 + dg * 32 + (g >> 1) * 16);
        ldmx4t(bv, sv + off);
#pragma unroll
        for (int hf = 0; hf < 2; hf++)
          mma16816h(o[dg * 2 + hf], pF, &bv[hf * 2]);
      }
    }
    __syncthreads();
  }

  // Epilogue: normalize, write fp16 ctx in the scrambled layout:
  //   ctx[b][h*128 + t/16][(t&15)*64 + d]
  const int b = bh >> 4;
  const int h = bh & 15;
#pragma unroll
  for (int r = 0; r < 2; r++) {
    const float inv = 1.0f / l_i[r];
    const int t = q0 + wid * 16 + (lane >> 2) + r * 8;
    const int row = h * 128 + (t >> 4);
    const size_t base = ((size_t)(b * Tn + row)) * En + ((t & 15) << 6);
#pragma unroll
    for (int dt = 0; dt < 8; dt++) {
      const int d = dt * 8 + (lane & 3) * 2;
      *(uint32_t*)(gctx + base + d) =
          cvt2h(o[dt][2 * r] * inv, o[dt][2 * r + 1] * inv);
    }
  }
}

// ---------------------------------------------------------------------------
extern "C" void kernel_launch(void* const* d_in, const int* in_sizes, int n_in,
                              void* d_out, int out_size) {
  const float* x     = (const float*)d_in[0];  // (T, B, E)
  const float* w_in  = (const float*)d_in[1];  // (E, 3E)
  const float* b_in  = (const float*)d_in[2];  // (3E)
  const float* w_out = (const float*)d_in[3];  // (E, E)
  const float* b_out = (const float*)d_in[4];  // (E)
  float* out = (float*)d_out;                  // (B, T, E)

  cudaFuncSetAttribute(hmma_gemm, cudaFuncAttributeMaxDynamicSharedMemorySize,
                       GEMM_SMEM);
  cudaFuncSetAttribute(attn_hmma, cudaFuncAttributeMaxDynamicSharedMemorySize,
                       ATTN_SMEM);

  // fp16 conversions
  cvt_x<<<(Mrows * Kdim / 4 + 255) / 256, 256>>>(x);
  cvt_transpose<<<dim3(Pn / 32, Kdim / 32), dim3(32, 8)>>>(w_in, 0);
  cvt_transpose<<<dim3(En / 32, Kdim / 32), dim3(32, 8)>>>(w_out, 1);

  // 1) QKV projection (fp16 1-pass HMMA) -> q/k/v fp16 (q pre-scaled 1/8)
  hmma_gemm<<<dim3(Pn / 128, Mrows / 256), 256, GEMM_SMEM>>>(b_in, nullptr, 0);
  // 2) Attention (fp16 HMMA flash, 1-pass, 2 CTAs/SM) -> ctx fp16
  attn_hmma<<<dim3(Tn / 128, BHn), 256, ATTN_SMEM>>>();
  // 3) Output projection (fp16 1-pass HMMA): M=4096, N=1024, K=1024
  hmma_gemm<<<dim3(En / 128, Mrows / 256), 256, GEMM_SMEM>>>(b_out, out, 1);
}

// round 13
// speedup vs baseline: 3.6792x; 1.0417x over previous
#include <cuda_runtime.h>
#include <cuda_fp16.h>
#include <math.h>
#include <cstdint>

// Problem dims (fixed by the reference)
#define Tn 2048
#define Bn 2
#define En 1024
#define Hn 16
#define Dn 64
#define BHn 32          // B*H
#define Pn 3072         // 3*E
#define Kdim 1024       // K of both GEMMs
#define Mrows 4096      // T*B

// ---------------------------------------------------------------------------
// Scratch: __device__ globals (allocation-free, graph-capturable)
// ---------------------------------------------------------------------------
__device__ __half gx[(size_t)Mrows * Kdim];
__device__ __half gwin[(size_t)Pn * Kdim];   // in_proj_w^T [N][K]
__device__ __half gwout[(size_t)En * Kdim];  // out_w^T     [N][K]
__device__ __half gctx[(size_t)Mrows * Kdim];
// attention operands, layout [(b*H+h)][t][d]; q pre-scaled by 0.125
__device__ __half gq[(size_t)BHn * Tn * Dn];
__device__ __half gk[(size_t)BHn * Tn * Dn];
__device__ __half gv[(size_t)BHn * Tn * Dn];

// ---------------------------------------------------------------------------
// PTX helpers (sm_103-safe: mma.sync + ldmatrix + cp.async only)
// ---------------------------------------------------------------------------
__device__ __forceinline__ uint32_t smem_u32(const void* p) {
  uint32_t a;
  asm("{ .reg .u64 t; cvta.to.shared.u64 t, %1; cvt.u32.u64 %0, t; }"
      : "=r"(a) : "l"(p));
  return a;
}

#define SW128(off) ((uint32_t)(off) ^ ((((uint32_t)(off)) >> 3) & 0x70))

#define CP_ASYNC16(dst, src)                                       \
  asm volatile("cp.async.cg.shared.global [%0], [%1], 16;"         \
               :: "r"(dst), "l"(src) : "memory")
#define CP_COMMIT() asm volatile("cp.async.commit_group;" ::: "memory")
#define CP_WAIT(n) asm volatile("cp.async.wait_group %0;" :: "n"(n) : "memory")

__device__ __forceinline__ void ldmx4(uint32_t* r, uint32_t addr) {
  asm volatile(
      "ldmatrix.sync.aligned.m8n8.x4.shared.b16 {%0,%1,%2,%3}, [%4];"
      : "=r"(r[0]), "=r"(r[1]), "=r"(r[2]), "=r"(r[3]) : "r"(addr));
}
__device__ __forceinline__ void ldmx4t(uint32_t* r, uint32_t addr) {
  asm volatile(
      "ldmatrix.sync.aligned.m8n8.x4.trans.shared.b16 {%0,%1,%2,%3}, [%4];"
      : "=r"(r[0]), "=r"(r[1]), "=r"(r[2]), "=r"(r[3]) : "r"(addr));
}

// fp16 MMA, fp32 accumulate
__device__ __forceinline__ void mma16816h(float* c, const uint32_t* a,
                                          const uint32_t* b) {
  asm volatile(
      "mma.sync.aligned.m16n8k16.row.col.f32.f16.f16.f32 "
      "{%0,%1,%2,%3}, {%4,%5,%6,%7}, {%8,%9}, {%0,%1,%2,%3};"
      : "+f"(c[0]), "+f"(c[1]), "+f"(c[2]), "+f"(c[3])
      : "r"(a[0]), "r"(a[1]), "r"(a[2]), "r"(a[3]), "r"(b[0]), "r"(b[1]));
}

__device__ __forceinline__ uint32_t cvt2h(float p0, float p1) {
  __half2 hh = __float22half2_rn(make_float2(p0, p1));
  return *(uint32_t*)&hh;
}

// ---------------------------------------------------------------------------
// Merged conversion kernel: one launch does x->fp16 and both W transposes.
// Block ranges: [0,4096) cvt_x, [4096,7168) w_in^T, [7168,8192) w_out^T.
// ---------------------------------------------------------------------------
#define CVT_X_BLOCKS 4096
#define CVT_WIN_BLOCKS 3072   // (Pn/32) * (Kdim/32) = 96*32
#define CVT_WOUT_BLOCKS 1024  // (En/32) * (Kdim/32) = 32*32
#define CVT_TOTAL (CVT_X_BLOCKS + CVT_WIN_BLOCKS + CVT_WOUT_BLOCKS)

__global__ __launch_bounds__(256) void cvt_all(
    const float* __restrict__ xin, const float* __restrict__ w_in,
    const float* __restrict__ w_out) {
  const int b = blockIdx.x;
  const int tid = threadIdx.x;
  if (b < CVT_X_BLOCKS) {
    size_t i = ((size_t)b * 256 + tid) * 4;
    float4 v = *(const float4*)(xin + i);
    uint2 hw = make_uint2(cvt2h(v.x, v.y), cvt2h(v.z, v.w));
    *(uint2*)(gx + i) = hw;
    return;
  }
  // transpose path: W[K][N] -> Wt[N][K]
  __shared__ float t[32][33];
  const float* W;
  __half* dst;
  int N, bb;
  if (b < CVT_X_BLOCKS + CVT_WIN_BLOCKS) {
    bb = b - CVT_X_BLOCKS;
    W = w_in; dst = gwin; N = Pn;
  } else {
    bb = b - CVT_X_BLOCKS - CVT_WIN_BLOCKS;
    W = w_out; dst = gwout; N = En;
  }
  const int nblk = N / 32;
  const int n0 = (bb % nblk) * 32, k0 = (bb / nblk) * 32;
  const int tx = tid & 31, ty = tid >> 5;  // 32 x 8
#pragma unroll
  for (int i = ty; i < 32; i += 8)
    t[i][tx] = W[(size_t)(k0 + i) * N + n0 + tx];
  __syncthreads();
#pragma unroll
  for (int j = ty; j < 32; j += 8)
    dst[(size_t)(n0 + j) * Kdim + k0 + tx] = __float2half(t[tx][j]);
}

// ---------------------------------------------------------------------------
// fp16 HMMA GEMM (single-pass): per CTA D[256 x 128] = A[M,K] * B^T[N,K] + bias
// BK=128 (two BK=64 sub-chunks per stage), double-buffered, ONE sync/chunk:
//   wait(chunk c) -> sync -> issue loads(c+1) -> compute(c).
// Stage = A(2x32KB) + B(2x16KB) = 96KB; 2 stages = 192KB smem.
// ---------------------------------------------------------------------------
#define GOFF_A 0            // A sub0 at 0, A sub1 at 32768
#define GOFF_B 65536        // B sub0 at 65536, B sub1 at 81920
#define GSUB_A 32768
#define GSUB_B 16384
#define GSTAGE 98304
#define GEMM_SMEM (2 * GSTAGE)  // 192 KB
#define NCHUNK (Kdim / 128)     // 8

__device__ __forceinline__ void gemm_load_sub(
    uint32_t sb, int sub, int k0, int tid,
    const __half* __restrict__ A, const __half* __restrict__ B,
    int m0, int n0) {
  const uint32_t abase = sb + GOFF_A + sub * GSUB_A;
  const uint32_t bbase = sb + GOFF_B + sub * GSUB_B;
#pragma unroll
  for (int it = 0; it < 8; it++) {      // A: 256 rows x 8 segs of 16B
    const int v = tid + it * 256;
    const int row = v >> 3, seg = v & 7;
    const uint32_t sw = SW128(row * 128 + seg * 16);
    CP_ASYNC16(abase + sw, A + (size_t)(m0 + row) * Kdim + k0 + seg * 8);
  }
#pragma unroll
  for (int it = 0; it < 4; it++) {      // B: 128 rows x 8 segs of 16B
    const int v = tid + it * 256;
    const int row = v >> 3, seg = v & 7;
    const uint32_t sw = SW128(row * 128 + seg * 16);
    CP_ASYNC16(bbase + sw, B + (size_t)(n0 + row) * Kdim + k0 + seg * 8);
  }
}

__global__ __launch_bounds__(256) void hmma_gemm(
    const float* __restrict__ bias, float* __restrict__ out, int mode) {
  extern __shared__ __align__(1024) char smc[];
  const uint32_t smem_base = smem_u32(smc);
  const int tid = threadIdx.x;
  const int wid = tid >> 5;
  const int lane = tid & 31;
  const int m0 = blockIdx.y * 256;
  const int n0 = blockIdx.x * 128;
  const int wm = (wid & 3) * 64;   // 4 warps along M
  const int wn = (wid >> 2) * 64;  // 2 warps along N

  const __half* A = (mode == 0) ? gx : gctx;
  const __half* B = (mode == 0) ? gwin : gwout;

  float acc[4][8][4];
#pragma unroll
  for (int i = 0; i < 4; i++)
#pragma unroll
    for (int j = 0; j < 8; j++)
#pragma unroll
      for (int c = 0; c < 4; c++) acc[i][j][c] = 0.f;

  const int g = lane >> 3;
  const int rr = lane & 7;

  gemm_load_sub(smem_base, 0, 0, tid, A, B, m0, n0);
  gemm_load_sub(smem_base, 1, 64, tid, A, B, m0, n0);
  CP_COMMIT();

  for (int c = 0; c < NCHUNK; c++) {
    const int buf = c & 1;
    CP_WAIT(0);          // chunk c fully arrived
    __syncthreads();     // all warps done with chunk c-1 (other buffer) + visibility
    if (c < NCHUNK - 1) {
      const uint32_t nb = smem_base + (1 - buf) * GSTAGE;
      gemm_load_sub(nb, 0, (c + 1) * 128, tid, A, B, m0, n0);
      gemm_load_sub(nb, 1, (c + 1) * 128 + 64, tid, A, B, m0, n0);
      CP_COMMIT();
    }

    const uint32_t sb = smem_base + buf * GSTAGE;
#pragma unroll
    for (int ks = 0; ks < 8; ks++) {
      const int sub = ks >> 2;
      const int kq = ks & 3;
      const uint32_t abase = sb + GOFF_A + sub * GSUB_A;
      const uint32_t bbase = sb + GOFF_B + sub * GSUB_B;
      uint32_t aF[4][4], bF[4][4];
#pragma unroll
      for (int i = 0; i < 4; i++) {
        int row = wm + i * 16 + (g & 1) * 8 + rr;
        ldmx4(aF[i], abase + SW128(row * 128 + kq * 32 + (g >> 1) * 16));
      }
#pragma unroll
      for (int jj = 0; jj < 4; jj++) {
        int row = wn + jj * 16 + (g >> 1) * 8 + rr;
        ldmx4(bF[jj], bbase + SW128(row * 128 + kq * 32 + (g & 1) * 16));
      }
#pragma unroll
      for (int i = 0; i < 4; i++)
#pragma unroll
        for (int j = 0; j < 8; j++)
          mma16816h(acc[i][j], aF[i], &bF[j >> 1][(j & 1) * 2]);
    }
  }

  // Epilogue (acc in registers; no smem dependence)
#pragma unroll
  for (int i = 0; i < 4; i++) {
#pragma unroll
    for (int j = 0; j < 8; j++) {
      const int mr = m0 + wm + i * 16 + (lane >> 2);
      const int f = n0 + wn + j * 8 + (lane & 3) * 2;
      const float b0 = bias[f], b1 = bias[f + 1];
      float p00 = acc[i][j][0] + b0, p01 = acc[i][j][1] + b1;
      float p10 = acc[i][j][2] + b0, p11 = acc[i][j][3] + b1;
      if (mode == 0) {
        const int which = f >> 10;
        const int h = (f & 1023) >> 6;
        const int d0 = f & 63;
        const int t0 = mr >> 1, bb0 = mr & 1;
        const int t1 = (mr + 8) >> 1, bb1 = (mr + 8) & 1;
        size_t i0 = ((size_t)(bb0 * Hn + h) * Tn + t0) * Dn + d0;
        size_t i1 = ((size_t)(bb1 * Hn + h) * Tn + t1) * Dn + d0;
        __half* dst = (which == 0) ? gq : (which == 1) ? gk : gv;
        const float sc = (which == 0) ? 0.125f : 1.f;
        *(uint32_t*)(dst + i0) = cvt2h(p00 * sc, p01 * sc);
        *(uint32_t*)(dst + i1) = cvt2h(p10 * sc, p11 * sc);
      } else {
        *(float2*)(out + (size_t)mr * En + f) = make_float2(p00, p01);
        *(float2*)(out + (size_t)(mr + 8) * En + f) = make_float2(p10, p11);
      }
    }
  }
}

// ---------------------------------------------------------------------------
// fp16 HMMA flash attention (single-pass): per CTA 128 queries x 1 head;
// 8 warps x 16 rows. K/V 64-key chunks, double-buffered SW128 smem, ONE
// sync/chunk (wait -> sync -> issue next -> compute). 48KB smem, 2 CTAs/SM.
// ---------------------------------------------------------------------------
#define A_OFF_K 0
#define A_OFF_V 8192
#define A_STAGE 16384
#define A_OFF_Q (2 * A_STAGE)          // 32768
#define ATTN_SMEM (2 * A_STAGE + 16384)  // 49152

__device__ __forceinline__ void attn_load_chunk(uint32_t sb, int stg, int j0,
                                                int tid, const __half* kp,
                                                const __half* vp) {
  const uint32_t base = sb + stg * A_STAGE;
#pragma unroll
  for (int it = 0; it < 2; it++) {
    int vec = tid + it * 256;       // 0..511
    int r = vec >> 3, seg = vec & 7;
    uint32_t sw = SW128(r * 128 + seg * 16);
    size_t gi = ((size_t)(j0 + r)) * Dn + seg * 8;
    CP_ASYNC16(base + A_OFF_K + sw, kp + gi);
    CP_ASYNC16(base + A_OFF_V + sw, vp + gi);
  }
}

__global__ __launch_bounds__(256, 2) void attn_hmma() {
  extern __shared__ __align__(1024) char smc[];
  const uint32_t sb = smem_u32(smc);
  const int tid = threadIdx.x;
  const int wid = tid >> 5;
  const int lane = tid & 31;
  const int g = lane >> 3;
  const int rr = lane & 7;
  const int bh = blockIdx.y;
  const int q0 = blockIdx.x * 128;

  const __half* qp = gq + (size_t)bh * Tn * Dn;
  const __half* kp = gk + (size_t)bh * Tn * Dn;
  const __half* vp = gv + (size_t)bh * Tn * Dn;

  // Preamble: Q tile + chunk 0, one commit group.
#pragma unroll
  for (int it = 0; it < 4; it++) {
    int vec = tid + it * 256;       // 0..1023
    int r = vec >> 3, seg = vec & 7;
    uint32_t sw = SW128(r * 128 + seg * 16);
    CP_ASYNC16(sb + A_OFF_Q + sw, qp + ((size_t)(q0 + r)) * Dn + seg * 8);
  }
  attn_load_chunk(sb, 0, 0, tid, kp, vp);
  CP_COMMIT();
  CP_WAIT(0);
  __syncthreads();

  // Q fragments held in registers for the whole key loop
  uint32_t qF[4][4];
#pragma unroll
  for (int ks = 0; ks < 4; ks++) {
    int row = wid * 16 + (g & 1) * 8 + rr;
    uint32_t off = SW128(row * 128 + ks * 32 + (g >> 1) * 16);
    ldmx4(qF[ks], sb + A_OFF_Q + off);
  }

  float o[8][4];
#pragma unroll
  for (int dt = 0; dt < 8; dt++)
#pragma unroll
    for (int c = 0; c < 4; c++) o[dt][c] = 0.f;
  float m_i[2] = {-1e30f, -1e30f};
  float l_i[2] = {0.f, 0.f};

  for (int c = 0; c < 32; c++) {
    const int buf = c & 1;
    if (c > 0) {
      CP_WAIT(0);        // chunk c arrived
      __syncthreads();   // all warps done with chunk c-1 (other buffer)
    }
    if (c < 31) {
      attn_load_chunk(sb, 1 - buf, (c + 1) * 64, tid, kp, vp);
      CP_COMMIT();
    }

    const uint32_t sk = sb + buf * A_STAGE + A_OFF_K;
    const uint32_t sv = sb + buf * A_STAGE + A_OFF_V;

    // ---- S = Q K^T (Q carries the 1/8) ----
    float s[8][4];
#pragma unroll
    for (int j = 0; j < 8; j++)
#pragma unroll
      for (int cc = 0; cc < 4; cc++) s[j][cc] = 0.f;

#pragma unroll
    for (int ks = 0; ks < 4; ks++) {
#pragma unroll
      for (int ng = 0; ng < 4; ng++) {
        uint32_t bk[4];
        int row = ng * 16 + (g >> 1) * 8 + rr;
        uint32_t off = SW128(row * 128 + ks * 32 + (g & 1) * 16);
        ldmx4(bk, sk + off);
#pragma unroll
        for (int hf = 0; hf < 2; hf++)
          mma16816h(s[ng * 2 + hf], qF[ks], &bk[hf * 2]);
      }
    }

    // ---- online softmax (rows: l/4 and l/4+8) ----
#pragma unroll
    for (int r = 0; r < 2; r++) {
      float mx = -1e30f;
#pragma unroll
      for (int j = 0; j < 8; j++)
        mx = fmaxf(mx, fmaxf(s[j][2 * r], s[j][2 * r + 1]));
      mx = fmaxf(mx, __shfl_xor_sync(0xffffffffu, mx, 1));
      mx = fmaxf(mx, __shfl_xor_sync(0xffffffffu, mx, 2));
      float mnew = fmaxf(m_i[r], mx);
      float corr = __expf(m_i[r] - mnew);
      m_i[r] = mnew;
      float rs = 0.f;
#pragma unroll
      for (int j = 0; j < 8; j++) {
        float p0 = __expf(s[j][2 * r] - mnew);
        float p1 = __expf(s[j][2 * r + 1] - mnew);
        s[j][2 * r] = p0;
        s[j][2 * r + 1] = p1;
        rs += p0 + p1;
      }
      rs += __shfl_xor_sync(0xffffffffu, rs, 1);
      rs += __shfl_xor_sync(0xffffffffu, rs, 2);
      l_i[r] = l_i[r] * corr + rs;
#pragma unroll
      for (int dt = 0; dt < 8; dt++) {
        o[dt][2 * r] *= corr;
        o[dt][2 * r + 1] *= corr;
      }
    }

    // ---- O += P V ----
#pragma unroll
    for (int kk = 0; kk < 4; kk++) {
      uint32_t pF[4];
      pF[0] = cvt2h(s[2 * kk][0], s[2 * kk][1]);
      pF[1] = cvt2h(s[2 * kk][2], s[2 * kk][3]);
      pF[2] = cvt2h(s[2 * kk + 1][0], s[2 * kk + 1][1]);
      pF[3] = cvt2h(s[2 * kk + 1][2], s[2 * kk + 1][3]);
#pragma unroll
      for (int dg = 0; dg < 4; dg++) {
        uint32_t bv[4];
        int keyrow = kk * 16 + (g & 1) * 8 + rr;
        uint32_t off = SW128(keyrow * 128 + dg * 32 + (g >> 1) * 16);
        ldmx4t(bv, sv + off);
#pragma unroll
        for (int hf = 0; hf < 2; hf++)
          mma16816h(o[dg * 2 + hf], pF, &bv[hf * 2]);
      }
    }
  }

  // Epilogue: normalize, write fp16 ctx in the scrambled layout:
  //   ctx[b][h*128 + t/16][(t&15)*64 + d]
  const int b = bh >> 4;
  const int h = bh & 15;
#pragma unroll
  for (int r = 0; r < 2; r++) {
    const float inv = 1.0f / l_i[r];
    const int t = q0 + wid * 16 + (lane >> 2) + r * 8;
    const int row = h * 128 + (t >> 4);
    const size_t base = ((size_t)(b * Tn + row)) * En + ((t & 15) << 6);
#pragma unroll
    for (int dt = 0; dt < 8; dt++) {
      const int d = dt * 8 + (lane & 3) * 2;
      *(uint32_t*)(gctx + base + d) =
          cvt2h(o[dt][2 * r] * inv, o[dt][2 * r + 1] * inv);
    }
  }
}

// ---------------------------------------------------------------------------
extern "C" void kernel_launch(void* const* d_in, const int* in_sizes, int n_in,
                              void* d_out, int out_size) {
  const float* x     = (const float*)d_in[0];  // (T, B, E)
  const float* w_in  = (const float*)d_in[1];  // (E, 3E)
  const float* b_in  = (const float*)d_in[2];  // (3E)
  const float* w_out = (const float*)d_in[3];  // (E, E)
  const float* b_out = (const float*)d_in[4];  // (E)
  float* out = (float*)d_out;                  // (B, T, E)

  cudaFuncSetAttribute(hmma_gemm, cudaFuncAttributeMaxDynamicSharedMemorySize,
                       GEMM_SMEM);
  cudaFuncSetAttribute(attn_hmma, cudaFuncAttributeMaxDynamicSharedMemorySize,
                       ATTN_SMEM);

  // fp16 conversions (one launch: x split + both weight transposes)
  cvt_all<<<CVT_TOTAL, 256>>>(x, w_in, w_out);

  // 1) QKV projection (fp16 1-pass HMMA) -> q/k/v fp16 (q pre-scaled 1/8)
  hmma_gemm<<<dim3(Pn / 128, Mrows / 256), 256, GEMM_SMEM>>>(b_in, nullptr, 0);
  // 2) Attention (fp16 HMMA flash, 1-pass, 2 CTAs/SM) -> ctx fp16
  attn_hmma<<<dim3(Tn / 128, BHn), 256, ATTN_SMEM>>>();
  // 3) Output projection (fp16 1-pass HMMA): M=4096, N=1024, K=1024
  hmma_gemm<<<dim3(En / 128, Mrows / 256), 256, GEMM_SMEM>>>(b_out, out, 1);
}

// round 14
// speedup vs baseline: 3.7258x; 1.0127x over previous
#include <cuda_runtime.h>
#include <cuda_fp16.h>
#include <math.h>
#include <cstdint>

// Problem dims (fixed by the reference)
#define Tn 2048
#define Bn 2
#define En 1024
#define Hn 16
#define Dn 64
#define BHn 32          // B*H
#define Pn 3072         // 3*E
#define Kdim 1024       // K of both GEMMs
#define Mrows 4096      // T*B

// q pre-scale: (1/sqrt(D)) * log2(e) so softmax runs in exp2 domain
#define QSCALE 0.18033688011112042f

// ---------------------------------------------------------------------------
// Scratch: __device__ globals (allocation-free, graph-capturable)
// ---------------------------------------------------------------------------
__device__ __half gx[(size_t)Mrows * Kdim];
__device__ __half gwin[(size_t)Pn * Kdim];   // in_proj_w^T [N][K]
__device__ __half gwout[(size_t)En * Kdim];  // out_w^T     [N][K]
__device__ __half gctx[(size_t)Mrows * Kdim];
// attention operands, layout [(b*H+h)][t][d]; q pre-scaled by QSCALE
__device__ __half gq[(size_t)BHn * Tn * Dn];
__device__ __half gk[(size_t)BHn * Tn * Dn];
__device__ __half gv[(size_t)BHn * Tn * Dn];

// ---------------------------------------------------------------------------
// PTX helpers (sm_103-safe: mma.sync + ldmatrix + cp.async only)
// ---------------------------------------------------------------------------
__device__ __forceinline__ uint32_t smem_u32(const void* p) {
  uint32_t a;
  asm("{ .reg .u64 t; cvta.to.shared.u64 t, %1; cvt.u32.u64 %0, t; }"
      : "=r"(a) : "l"(p));
  return a;
}

#define SW128(off) ((uint32_t)(off) ^ ((((uint32_t)(off)) >> 3) & 0x70))

#define CP_ASYNC16(dst, src)                                       \
  asm volatile("cp.async.cg.shared.global [%0], [%1], 16;"         \
               :: "r"(dst), "l"(src) : "memory")
#define CP_COMMIT() asm volatile("cp.async.commit_group;" ::: "memory")
#define CP_WAIT(n) asm volatile("cp.async.wait_group %0;" :: "n"(n) : "memory")

__device__ __forceinline__ void ldmx4(uint32_t* r, uint32_t addr) {
  asm volatile(
      "ldmatrix.sync.aligned.m8n8.x4.shared.b16 {%0,%1,%2,%3}, [%4];"
      : "=r"(r[0]), "=r"(r[1]), "=r"(r[2]), "=r"(r[3]) : "r"(addr));
}
__device__ __forceinline__ void ldmx4t(uint32_t* r, uint32_t addr) {
  asm volatile(
      "ldmatrix.sync.aligned.m8n8.x4.trans.shared.b16 {%0,%1,%2,%3}, [%4];"
      : "=r"(r[0]), "=r"(r[1]), "=r"(r[2]), "=r"(r[3]) : "r"(addr));
}

// fp16 MMA, fp32 accumulate
__device__ __forceinline__ void mma16816h(float* c, const uint32_t* a,
                                          const uint32_t* b) {
  asm volatile(
      "mma.sync.aligned.m16n8k16.row.col.f32.f16.f16.f32 "
      "{%0,%1,%2,%3}, {%4,%5,%6,%7}, {%8,%9}, {%0,%1,%2,%3};"
      : "+f"(c[0]), "+f"(c[1]), "+f"(c[2]), "+f"(c[3])
      : "r"(a[0]), "r"(a[1]), "r"(a[2]), "r"(a[3]), "r"(b[0]), "r"(b[1]));
}

__device__ __forceinline__ uint32_t cvt2h(float p0, float p1) {
  __half2 hh = __float22half2_rn(make_float2(p0, p1));
  return *(uint32_t*)&hh;
}

// ---------------------------------------------------------------------------
// Merged conversion kernel: one launch does x->fp16 and both W transposes.
// ---------------------------------------------------------------------------
#define CVT_X_BLOCKS 4096
#define CVT_WIN_BLOCKS 3072   // (Pn/32) * (Kdim/32)
#define CVT_WOUT_BLOCKS 1024  // (En/32) * (Kdim/32)
#define CVT_TOTAL (CVT_X_BLOCKS + CVT_WIN_BLOCKS + CVT_WOUT_BLOCKS)

__global__ __launch_bounds__(256) void cvt_all(
    const float* __restrict__ xin, const float* __restrict__ w_in,
    const float* __restrict__ w_out) {
  const int b = blockIdx.x;
  const int tid = threadIdx.x;
  if (b < CVT_X_BLOCKS) {
    size_t i = ((size_t)b * 256 + tid) * 4;
    float4 v = *(const float4*)(xin + i);
    uint2 hw = make_uint2(cvt2h(v.x, v.y), cvt2h(v.z, v.w));
    *(uint2*)(gx + i) = hw;
    return;
  }
  __shared__ float t[32][33];
  const float* W;
  __half* dst;
  int N, bb;
  if (b < CVT_X_BLOCKS + CVT_WIN_BLOCKS) {
    bb = b - CVT_X_BLOCKS;
    W = w_in; dst = gwin; N = Pn;
  } else {
    bb = b - CVT_X_BLOCKS - CVT_WIN_BLOCKS;
    W = w_out; dst = gwout; N = En;
  }
  const int nblk = N / 32;
  const int n0 = (bb % nblk) * 32, k0 = (bb / nblk) * 32;
  const int tx = tid & 31, ty = tid >> 5;
#pragma unroll
  for (int i = ty; i < 32; i += 8)
    t[i][tx] = W[(size_t)(k0 + i) * N + n0 + tx];
  __syncthreads();
#pragma unroll
  for (int j = ty; j < 32; j += 8)
    dst[(size_t)(n0 + j) * Kdim + k0 + tx] = __float2half(t[tx][j]);
}

// ---------------------------------------------------------------------------
// fp16 HMMA GEMM (single-pass): per CTA D[256 x 128] = A[M,K] * B^T[N,K] + bias
// BK=128 (two BK=64 sub-chunks), double-buffered, ONE sync/chunk.
// ---------------------------------------------------------------------------
#define GOFF_A 0
#define GOFF_B 65536
#define GSUB_A 32768
#define GSUB_B 16384
#define GSTAGE 98304
#define GEMM_SMEM (2 * GSTAGE)  // 192 KB
#define NCHUNK (Kdim / 128)     // 8

__device__ __forceinline__ void gemm_load_sub(
    uint32_t sb, int sub, int k0, int tid,
    const __half* __restrict__ A, const __half* __restrict__ B,
    int m0, int n0) {
  const uint32_t abase = sb + GOFF_A + sub * GSUB_A;
  const uint32_t bbase = sb + GOFF_B + sub * GSUB_B;
#pragma unroll
  for (int it = 0; it < 8; it++) {
    const int v = tid + it * 256;
    const int row = v >> 3, seg = v & 7;
    const uint32_t sw = SW128(row * 128 + seg * 16);
    CP_ASYNC16(abase + sw, A + (size_t)(m0 + row) * Kdim + k0 + seg * 8);
  }
#pragma unroll
  for (int it = 0; it < 4; it++) {
    const int v = tid + it * 256;
    const int row = v >> 3, seg = v & 7;
    const uint32_t sw = SW128(row * 128 + seg * 16);
    CP_ASYNC16(bbase + sw, B + (size_t)(n0 + row) * Kdim + k0 + seg * 8);
  }
}

__global__ __launch_bounds__(256) void hmma_gemm(
    const float* __restrict__ bias, float* __restrict__ out, int mode) {
  extern __shared__ __align__(1024) char smc[];
  const uint32_t smem_base = smem_u32(smc);
  const int tid = threadIdx.x;
  const int wid = tid >> 5;
  const int lane = tid & 31;
  const int m0 = blockIdx.y * 256;
  const int n0 = blockIdx.x * 128;
  const int wm = (wid & 3) * 64;
  const int wn = (wid >> 2) * 64;

  const __half* A = (mode == 0) ? gx : gctx;
  const __half* B = (mode == 0) ? gwin : gwout;

  float acc[4][8][4];
#pragma unroll
  for (int i = 0; i < 4; i++)
#pragma unroll
    for (int j = 0; j < 8; j++)
#pragma unroll
      for (int c = 0; c < 4; c++) acc[i][j][c] = 0.f;

  const int g = lane >> 3;
  const int rr = lane & 7;

  gemm_load_sub(smem_base, 0, 0, tid, A, B, m0, n0);
  gemm_load_sub(smem_base, 1, 64, tid, A, B, m0, n0);
  CP_COMMIT();

  for (int c = 0; c < NCHUNK; c++) {
    const int buf = c & 1;
    CP_WAIT(0);
    __syncthreads();
    if (c < NCHUNK - 1) {
      const uint32_t nb = smem_base + (1 - buf) * GSTAGE;
      gemm_load_sub(nb, 0, (c + 1) * 128, tid, A, B, m0, n0);
      gemm_load_sub(nb, 1, (c + 1) * 128 + 64, tid, A, B, m0, n0);
      CP_COMMIT();
    }

    const uint32_t sb = smem_base + buf * GSTAGE;
#pragma unroll
    for (int ks = 0; ks < 8; ks++) {
      const int sub = ks >> 2;
      const int kq = ks & 3;
      const uint32_t abase = sb + GOFF_A + sub * GSUB_A;
      const uint32_t bbase = sb + GOFF_B + sub * GSUB_B;
      uint32_t aF[4][4], bF[4][4];
#pragma unroll
      for (int i = 0; i < 4; i++) {
        int row = wm + i * 16 + (g & 1) * 8 + rr;
        ldmx4(aF[i], abase + SW128(row * 128 + kq * 32 + (g >> 1) * 16));
      }
#pragma unroll
      for (int jj = 0; jj < 4; jj++) {
        int row = wn + jj * 16 + (g >> 1) * 8 + rr;
        ldmx4(bF[jj], bbase + SW128(row * 128 + kq * 32 + (g & 1) * 16));
      }
#pragma unroll
      for (int i = 0; i < 4; i++)
#pragma unroll
        for (int j = 0; j < 8; j++)
          mma16816h(acc[i][j], aF[i], &bF[j >> 1][(j & 1) * 2]);
    }
  }

  // Epilogue
#pragma unroll
  for (int i = 0; i < 4; i++) {
#pragma unroll
    for (int j = 0; j < 8; j++) {
      const int mr = m0 + wm + i * 16 + (lane >> 2);
      const int f = n0 + wn + j * 8 + (lane & 3) * 2;
      const float b0 = bias[f], b1 = bias[f + 1];
      float p00 = acc[i][j][0] + b0, p01 = acc[i][j][1] + b1;
      float p10 = acc[i][j][2] + b0, p11 = acc[i][j][3] + b1;
      if (mode == 0) {
        const int which = f >> 10;
        const int h = (f & 1023) >> 6;
        const int d0 = f & 63;
        const int t0 = mr >> 1, bb0 = mr & 1;
        const int t1 = (mr + 8) >> 1, bb1 = (mr + 8) & 1;
        size_t i0 = ((size_t)(bb0 * Hn + h) * Tn + t0) * Dn + d0;
        size_t i1 = ((size_t)(bb1 * Hn + h) * Tn + t1) * Dn + d0;
        __half* dst = (which == 0) ? gq : (which == 1) ? gk : gv;
        const float sc = (which == 0) ? QSCALE : 1.f;
        *(uint32_t*)(dst + i0) = cvt2h(p00 * sc, p01 * sc);
        *(uint32_t*)(dst + i1) = cvt2h(p10 * sc, p11 * sc);
      } else {
        *(float2*)(out + (size_t)mr * En + f) = make_float2(p00, p01);
        *(float2*)(out + (size_t)(mr + 8) * En + f) = make_float2(p10, p11);
      }
    }
  }
}

// ---------------------------------------------------------------------------
// fp16 HMMA flash attention (single-pass, exp2 softmax): per CTA 128 queries
// x 1 head; 8 warps x 16 rows. K/V 64-key chunks, double-buffered, ONE
// sync/chunk. 48KB smem, 2 CTAs/SM. Logits are in log2 domain (q pre-scaled).
// ---------------------------------------------------------------------------
#define A_OFF_K 0
#define A_OFF_V 8192
#define A_STAGE 16384
#define A_OFF_Q (2 * A_STAGE)
#define ATTN_SMEM (2 * A_STAGE + 16384)  // 49152

__device__ __forceinline__ void attn_load_chunk(uint32_t sb, int stg, int j0,
                                                int tid, const __half* kp,
                                                const __half* vp) {
  const uint32_t base = sb + stg * A_STAGE;
#pragma unroll
  for (int it = 0; it < 2; it++) {
    int vec = tid + it * 256;
    int r = vec >> 3, seg = vec & 7;
    uint32_t sw = SW128(r * 128 + seg * 16);
    size_t gi = ((size_t)(j0 + r)) * Dn + seg * 8;
    CP_ASYNC16(base + A_OFF_K + sw, kp + gi);
    CP_ASYNC16(base + A_OFF_V + sw, vp + gi);
  }
}

__global__ __launch_bounds__(256, 2) void attn_hmma() {
  extern __shared__ __align__(1024) char smc[];
  const uint32_t sb = smem_u32(smc);
  const int tid = threadIdx.x;
  const int wid = tid >> 5;
  const int lane = tid & 31;
  const int g = lane >> 3;
  const int rr = lane & 7;
  const int bh = blockIdx.y;
  const int q0 = blockIdx.x * 128;

  const __half* qp = gq + (size_t)bh * Tn * Dn;
  const __half* kp = gk + (size_t)bh * Tn * Dn;
  const __half* vp = gv + (size_t)bh * Tn * Dn;

#pragma unroll
  for (int it = 0; it < 4; it++) {
    int vec = tid + it * 256;
    int r = vec >> 3, seg = vec & 7;
    uint32_t sw = SW128(r * 128 + seg * 16);
    CP_ASYNC16(sb + A_OFF_Q + sw, qp + ((size_t)(q0 + r)) * Dn + seg * 8);
  }
  attn_load_chunk(sb, 0, 0, tid, kp, vp);
  CP_COMMIT();
  CP_WAIT(0);
  __syncthreads();

  uint32_t qF[4][4];
#pragma unroll
  for (int ks = 0; ks < 4; ks++) {
    int row = wid * 16 + (g & 1) * 8 + rr;
    uint32_t off = SW128(row * 128 + ks * 32 + (g >> 1) * 16);
    ldmx4(qF[ks], sb + A_OFF_Q + off);
  }

  float o[8][4];
#pragma unroll
  for (int dt = 0; dt < 8; dt++)
#pragma unroll
    for (int c = 0; c < 4; c++) o[dt][c] = 0.f;
  float m_i[2] = {-1e30f, -1e30f};
  float l_i[2] = {0.f, 0.f};

  for (int c = 0; c < 32; c++) {
    const int buf = c & 1;
    if (c > 0) {
      CP_WAIT(0);
      __syncthreads();
    }
    if (c < 31) {
      attn_load_chunk(sb, 1 - buf, (c + 1) * 64, tid, kp, vp);
      CP_COMMIT();
    }

    const uint32_t sk = sb + buf * A_STAGE + A_OFF_K;
    const uint32_t sv = sb + buf * A_STAGE + A_OFF_V;

    // ---- S = Q K^T (log2-domain logits) ----
    float s[8][4];
#pragma unroll
    for (int j = 0; j < 8; j++)
#pragma unroll
      for (int cc = 0; cc < 4; cc++) s[j][cc] = 0.f;

#pragma unroll
    for (int ks = 0; ks < 4; ks++) {
#pragma unroll
      for (int ng = 0; ng < 4; ng++) {
        uint32_t bk[4];
        int row = ng * 16 + (g >> 1) * 8 + rr;
        uint32_t off = SW128(row * 128 + ks * 32 + (g & 1) * 16);
        ldmx4(bk, sk + off);
#pragma unroll
        for (int hf = 0; hf < 2; hf++)
          mma16816h(s[ng * 2 + hf], qF[ks], &bk[hf * 2]);
      }
    }

    // ---- online softmax in exp2 domain (rows: l/4 and l/4+8) ----
#pragma unroll
    for (int r = 0; r < 2; r++) {
      float mx = -1e30f;
#pragma unroll
      for (int j = 0; j < 8; j++)
        mx = fmaxf(mx, fmaxf(s[j][2 * r], s[j][2 * r + 1]));
      mx = fmaxf(mx, __shfl_xor_sync(0xffffffffu, mx, 1));
      mx = fmaxf(mx, __shfl_xor_sync(0xffffffffu, mx, 2));
      float mnew = fmaxf(m_i[r], mx);
      float corr = exp2f(m_i[r] - mnew);
      m_i[r] = mnew;
      float rs = 0.f;
#pragma unroll
      for (int j = 0; j < 8; j++) {
        float p0 = exp2f(s[j][2 * r] - mnew);
        float p1 = exp2f(s[j][2 * r + 1] - mnew);
        s[j][2 * r] = p0;
        s[j][2 * r + 1] = p1;
        rs += p0 + p1;
      }
      rs += __shfl_xor_sync(0xffffffffu, rs, 1);
      rs += __shfl_xor_sync(0xffffffffu, rs, 2);
      l_i[r] = l_i[r] * corr + rs;
      if (corr != 1.0f) {  // skip rescale once running max is stable
#pragma unroll
        for (int dt = 0; dt < 8; dt++) {
          o[dt][2 * r] *= corr;
          o[dt][2 * r + 1] *= corr;
        }
      }
    }

    // ---- O += P V ----
#pragma unroll
    for (int kk = 0; kk < 4; kk++) {
      uint32_t pF[4];
      pF[0] = cvt2h(s[2 * kk][0], s[2 * kk][1]);
      pF[1] = cvt2h(s[2 * kk][2], s[2 * kk][3]);
      pF[2] = cvt2h(s[2 * kk + 1][0], s[2 * kk + 1][1]);
      pF[3] = cvt2h(s[2 * kk + 1][2], s[2 * kk + 1][3]);
#pragma unroll
      for (int dg = 0; dg < 4; dg++) {
        uint32_t bv[4];
        int keyrow = kk * 16 + (g & 1) * 8 + rr;
        uint32_t off = SW128(keyrow * 128 + dg * 32 + (g >> 1) * 16);
        ldmx4t(bv, sv + off);
#pragma unroll
        for (int hf = 0; hf < 2; hf++)
          mma16816h(o[dg * 2 + hf], pF, &bv[hf * 2]);
      }
    }
  }

  // Epilogue: normalize, write fp16 ctx in the scrambled layout:
  //   ctx[b][h*128 + t/16][(t&15)*64 + d]
  const int b = bh >> 4;
  const int h = bh & 15;
#pragma unroll
  for (int r = 0; r < 2; r++) {
    const float inv = 1.0f / l_i[r];
    const int t = q0 + wid * 16 + (lane >> 2) + r * 8;
    const int row = h * 128 + (t >> 4);
    const size_t base = ((size_t)(b * Tn + row)) * En + ((t & 15) << 6);
#pragma unroll
    for (int dt = 0; dt < 8; dt++) {
      const int d = dt * 8 + (lane & 3) * 2;
      *(uint32_t*)(gctx + base + d) =
          cvt2h(o[dt][2 * r] * inv, o[dt][2 * r + 1] * inv);
    }
  }
}

// ---------------------------------------------------------------------------
extern "C" void kernel_launch(void* const* d_in, const int* in_sizes, int n_in,
                              void* d_out, int out_size) {
  const float* x     = (const float*)d_in[0];  // (T, B, E)
  const float* w_in  = (const float*)d_in[1];  // (E, 3E)
  const float* b_in  = (const float*)d_in[2];  // (3E)
  const float* w_out = (const float*)d_in[3];  // (E, E)
  const float* b_out = (const float*)d_in[4];  // (E)
  float* out = (float*)d_out;                  // (B, T, E)

  cudaFuncSetAttribute(hmma_gemm, cudaFuncAttributeMaxDynamicSharedMemorySize,
                       GEMM_SMEM);
  cudaFuncSetAttribute(attn_hmma, cudaFuncAttributeMaxDynamicSharedMemorySize,
                       ATTN_SMEM);

  // fp16 conversions (one launch: x + both weight transposes)
  cvt_all<<<CVT_TOTAL, 256>>>(x, w_in, w_out);

  // 1) QKV projection (fp16 1-pass HMMA) -> q/k/v fp16 (q pre-scaled QSCALE)
  hmma_gemm<<<dim3(Pn / 128, Mrows / 256), 256, GEMM_SMEM>>>(b_in, nullptr, 0);
  // 2) Attention (fp16 HMMA flash, exp2 softmax, 2 CTAs/SM) -> ctx fp16
  attn_hmma<<<dim3(Tn / 128, BHn), 256, ATTN_SMEM>>>();
  // 3) Output projection (fp16 1-pass HMMA): M=4096, N=1024, K=1024
  hmma_gemm<<<dim3(En / 128, Mrows / 256), 256, GEMM_SMEM>>>(b_out, out, 1);
}